// round 2
// baseline (speedup 1.0000x reference)
#include <cuda_runtime.h>
#include <cuda_bf16.h>

// Problem constants
#define BB 4
#define TT 2048
#define DD 512
#define HH 8
#define HD 64
#define MM (BB * TT)      // 8192 rows
// GEMM tiling
#define BMT 64
#define BNT 64
#define BKT 32

// Scratch (device globals: no allocation allowed)
__device__ float g_Qd[BB * HH * HD * TT];  // d-major: [bh][d][t]
__device__ float g_Kd[BB * HH * HD * TT];  // d-major: [bh][d][t]
__device__ float g_V [BB * HH * TT * HD];  // natural: [bh][t][d]
__device__ float g_Ctx[MM * DD];           // [b*T+t][h*64+d]

// ---------------------------------------------------------------------------
// Generic GEMM:  out = A[M,K] * W[N,K]^T + bias, with epilogue modes:
//   mode 0: plain row-major [M,N] (final output projection)
//   mode 1: scatter to [b][h][t][d]  (V)
//   mode 2: transpose-scatter to [b][h][d][t]  (Q, K; scale folded in)
// ---------------------------------------------------------------------------
__global__ void __launch_bounds__(256)
gemm_kernel(const float* __restrict__ A, const float* __restrict__ W,
            const float* __restrict__ bias, float* __restrict__ out,
            float scale, int mode)
{
    __shared__ float smem_u[2 * BKT * (BMT + 4)];   // 4352 floats, aliased
    float* As = smem_u;                  // [BKT][68]  (k-major: As[k][m])
    float* Bs = smem_u + BKT * (BMT + 4);// [BKT][68]  (k-major: Bs[k][n])
    const int SP = BMT + 4;              // 68

    const int tid = threadIdx.x;
    const int tx = tid & 15, ty = tid >> 4;
    const int m0 = blockIdx.x * BMT;
    const int n0 = blockIdx.y * BNT;

    float acc[4][4];
#pragma unroll
    for (int i = 0; i < 4; i++)
#pragma unroll
        for (int j = 0; j < 4; j++) acc[i][j] = 0.f;

    for (int kt = 0; kt < DD / BKT; kt++) {
        const int k0 = kt * BKT;
        __syncthreads();
        // load A tile (64 rows x 32 k) transposed into As[k][m]
#pragma unroll
        for (int l = 0; l < 2; l++) {
            int f = tid + l * 256;
            int row = f >> 3, c4 = (f & 7) * 4;
            float4 v = *(const float4*)&A[(m0 + row) * DD + k0 + c4];
            As[(c4 + 0) * SP + row] = v.x;
            As[(c4 + 1) * SP + row] = v.y;
            As[(c4 + 2) * SP + row] = v.z;
            As[(c4 + 3) * SP + row] = v.w;
        }
        // load W tile (64 rows x 32 k) transposed into Bs[k][n]
#pragma unroll
        for (int l = 0; l < 2; l++) {
            int f = tid + l * 256;
            int row = f >> 3, c4 = (f & 7) * 4;
            float4 v = *(const float4*)&W[(n0 + row) * DD + k0 + c4];
            Bs[(c4 + 0) * SP + row] = v.x;
            Bs[(c4 + 1) * SP + row] = v.y;
            Bs[(c4 + 2) * SP + row] = v.z;
            Bs[(c4 + 3) * SP + row] = v.w;
        }
        __syncthreads();
#pragma unroll
        for (int kk = 0; kk < BKT; kk++) {
            float4 a4 = *(const float4*)&As[kk * SP + ty * 4];
            float4 b4 = *(const float4*)&Bs[kk * SP + tx * 4];
            float a[4] = {a4.x, a4.y, a4.z, a4.w};
            float b[4] = {b4.x, b4.y, b4.z, b4.w};
#pragma unroll
            for (int i = 0; i < 4; i++)
#pragma unroll
                for (int j = 0; j < 4; j++) acc[i][j] += a[i] * b[j];
        }
    }

    // bias + scale
    float bi[4];
#pragma unroll
    for (int j = 0; j < 4; j++) bi[j] = bias[n0 + tx * 4 + j];
#pragma unroll
    for (int i = 0; i < 4; i++)
#pragma unroll
        for (int j = 0; j < 4; j++) acc[i][j] = (acc[i][j] + bi[j]) * scale;

    if (mode == 0) {
#pragma unroll
        for (int i = 0; i < 4; i++) {
            float4 v = make_float4(acc[i][0], acc[i][1], acc[i][2], acc[i][3]);
            *(float4*)&out[(m0 + ty * 4 + i) * DD + n0 + tx * 4] = v;
        }
    } else if (mode == 1) {
        // V: [b][h][t][d]
        int b = m0 >> 11;            // m0 / 2048
        int h = n0 >> 6;             // n0 / 64
        int tb = m0 & 2047;
#pragma unroll
        for (int i = 0; i < 4; i++) {
            float4 v = make_float4(acc[i][0], acc[i][1], acc[i][2], acc[i][3]);
            int t = tb + ty * 4 + i;
            *(float4*)&out[(((b * HH + h) * TT) + t) * HD + tx * 4] = v;
        }
    } else {
        // Q/K: transpose through smem to [b][h][d][t]
        float* Ts = smem_u;          // [64][68]
        __syncthreads();
#pragma unroll
        for (int i = 0; i < 4; i++)
#pragma unroll
            for (int j = 0; j < 4; j++)
                Ts[(tx * 4 + j) * SP + ty * 4 + i] = acc[i][j];
        __syncthreads();
        int b = m0 >> 11;
        int h = n0 >> 6;
        int tb = m0 & 2047;
        float* base = out + (size_t)((b * HH + h) * HD) * TT;
#pragma unroll
        for (int rr = 0; rr < 4; rr++) {
            int dloc = (tid >> 4) + rr * 16;
            int c4 = (tid & 15) * 4;
            float4 v = *(const float4*)&Ts[dloc * SP + c4];
            *(float4*)&base[dloc * TT + tb + c4] = v;
        }
    }
}

// ---------------------------------------------------------------------------
// Flash attention: one block = (64 queries) x (one (b,h)); streams K/V tiles.
// Q,K are d-major [bh][64][2048]; V natural [bh][2048][64].
// Output scattered to Ctx[b*T+t][h*64+d].
// ---------------------------------------------------------------------------
#define ASP 68
#define ATTN_SMEM (4 * 64 * ASP * 4)

__global__ void __launch_bounds__(256)
attn_kernel(const float* __restrict__ Qd, const float* __restrict__ Kd,
            const float* __restrict__ V, float* __restrict__ Ctx)
{
    extern __shared__ float sm[];
    float* Qs = sm;               // [d][i]
    float* Ks = sm + 64 * ASP;    // [d][j]
    float* Vs = sm + 2 * 64 * ASP;// [j][d]
    float* Ps = sm + 3 * 64 * ASP;// [i][j]

    const int tid = threadIdx.x;
    const int tx = tid & 15, ty = tid >> 4;
    const int qt = blockIdx.x;    // 0..31
    const int bh = blockIdx.y;    // 0..31

    const float* Qh = Qd + (size_t)bh * HD * TT;
    const float* Kh = Kd + (size_t)bh * HD * TT;
    const float* Vh = V  + (size_t)bh * TT * HD;

    // Load Q tile: Qs[d][i] = Qh[d][qt*64 + i]
    {
        int r = tid >> 4, c4 = (tid & 15) * 4;
#pragma unroll
        for (int rr = 0; rr < 4; rr++) {
            int d = r + rr * 16;
            *(float4*)&Qs[d * ASP + c4] =
                *(const float4*)&Qh[d * TT + qt * 64 + c4];
        }
    }

    float o[4][4];
    float mrow[4], lrow[4];
#pragma unroll
    for (int i = 0; i < 4; i++) {
        mrow[i] = -1e30f; lrow[i] = 0.f;
#pragma unroll
        for (int j = 0; j < 4; j++) o[i][j] = 0.f;
    }

    for (int kt = 0; kt < TT / 64; kt++) {
        __syncthreads();
        {
            int r = tid >> 4, c4 = (tid & 15) * 4;
#pragma unroll
            for (int rr = 0; rr < 4; rr++) {
                int d = r + rr * 16;
                *(float4*)&Ks[d * ASP + c4] =
                    *(const float4*)&Kh[d * TT + kt * 64 + c4];
            }
#pragma unroll
            for (int rr = 0; rr < 4; rr++) {
                int j = r + rr * 16;
                *(float4*)&Vs[j * ASP + c4] =
                    *(const float4*)&Vh[(kt * 64 + j) * HD + c4];
            }
        }
        __syncthreads();

        // S = Q . K  (contraction over d; scale already folded into Q)
        float s[4][4];
#pragma unroll
        for (int i = 0; i < 4; i++)
#pragma unroll
            for (int j = 0; j < 4; j++) s[i][j] = 0.f;
#pragma unroll 16
        for (int d = 0; d < 64; d++) {
            float4 q4 = *(const float4*)&Qs[d * ASP + ty * 4];
            float4 k4 = *(const float4*)&Ks[d * ASP + tx * 4];
            float qa[4] = {q4.x, q4.y, q4.z, q4.w};
            float kb[4] = {k4.x, k4.y, k4.z, k4.w};
#pragma unroll
            for (int i = 0; i < 4; i++)
#pragma unroll
                for (int j = 0; j < 4; j++) s[i][j] += qa[i] * kb[j];
        }

        // Online softmax per row (row split across 16 tx lanes)
#pragma unroll
        for (int i = 0; i < 4; i++) {
            float mx = fmaxf(fmaxf(s[i][0], s[i][1]), fmaxf(s[i][2], s[i][3]));
#pragma unroll
            for (int off = 8; off > 0; off >>= 1)
                mx = fmaxf(mx, __shfl_xor_sync(0xffffffffu, mx, off));
            float mnew = fmaxf(mrow[i], mx);
            float corr = __expf(mrow[i] - mnew);
            float ps = 0.f;
#pragma unroll
            for (int j = 0; j < 4; j++) {
                float e = __expf(s[i][j] - mnew);
                s[i][j] = e;
                ps += e;
            }
#pragma unroll
            for (int off = 8; off > 0; off >>= 1)
                ps += __shfl_xor_sync(0xffffffffu, ps, off);
            lrow[i] = lrow[i] * corr + ps;
            mrow[i] = mnew;
#pragma unroll
            for (int j = 0; j < 4; j++) o[i][j] *= corr;
        }

        // P -> smem (conflict-free float4)
#pragma unroll
        for (int i = 0; i < 4; i++) {
            float4 p = make_float4(s[i][0], s[i][1], s[i][2], s[i][3]);
            *(float4*)&Ps[(ty * 4 + i) * ASP + tx * 4] = p;
        }
        __syncthreads();

        // O += P * V  (contraction over j)
#pragma unroll
        for (int j4 = 0; j4 < 64; j4 += 4) {
            float4 v0 = *(const float4*)&Vs[(j4 + 0) * ASP + tx * 4];
            float4 v1 = *(const float4*)&Vs[(j4 + 1) * ASP + tx * 4];
            float4 v2 = *(const float4*)&Vs[(j4 + 2) * ASP + tx * 4];
            float4 v3 = *(const float4*)&Vs[(j4 + 3) * ASP + tx * 4];
#pragma unroll
            for (int i = 0; i < 4; i++) {
                float4 p4 = *(const float4*)&Ps[(ty * 4 + i) * ASP + j4];
                o[i][0] += p4.x * v0.x + p4.y * v1.x + p4.z * v2.x + p4.w * v3.x;
                o[i][1] += p4.x * v0.y + p4.y * v1.y + p4.z * v2.y + p4.w * v3.y;
                o[i][2] += p4.x * v0.z + p4.y * v1.z + p4.z * v2.z + p4.w * v3.z;
                o[i][3] += p4.x * v0.w + p4.y * v1.w + p4.z * v2.w + p4.w * v3.w;
            }
        }
    }

    // Normalize + write Ctx[b*T+t][h*64+d]
    const int b = bh >> 3, h = bh & 7;
#pragma unroll
    for (int i = 0; i < 4; i++) {
        float inv = 1.f / lrow[i];
        int t = qt * 64 + ty * 4 + i;
        float4 v = make_float4(o[i][0] * inv, o[i][1] * inv,
                               o[i][2] * inv, o[i][3] * inv);
        *(float4*)&Ctx[(size_t)(b * TT + t) * DD + h * HD + tx * 4] = v;
    }
}

// ---------------------------------------------------------------------------
extern "C" void kernel_launch(void* const* d_in, const int* in_sizes, int n_in,
                              void* d_out, int out_size)
{
    const float* x  = (const float*)d_in[0];
    const float* wq = (const float*)d_in[1];
    const float* bq = (const float*)d_in[2];
    const float* wk = (const float*)d_in[3];
    const float* bk = (const float*)d_in[4];
    const float* wv = (const float*)d_in[5];
    const float* bv = (const float*)d_in[6];
    const float* wo = (const float*)d_in[7];
    const float* bo = (const float*)d_in[8];
    float* out = (float*)d_out;

    float *pQ, *pK, *pV, *pC;
    cudaGetSymbolAddress((void**)&pQ, g_Qd);
    cudaGetSymbolAddress((void**)&pK, g_Kd);
    cudaGetSymbolAddress((void**)&pV, g_V);
    cudaGetSymbolAddress((void**)&pC, g_Ctx);

    dim3 gg(MM / BMT, DD / BNT);   // 128 x 8
    const float qscale = 0.125f;   // 1/sqrt(HD)

    gemm_kernel<<<gg, 256>>>(x, wq, bq, pQ, qscale, 2);
    gemm_kernel<<<gg, 256>>>(x, wk, bk, pK, 1.0f, 2);
    gemm_kernel<<<gg, 256>>>(x, wv, bv, pV, 1.0f, 1);

    cudaFuncSetAttribute(attn_kernel,
                         cudaFuncAttributeMaxDynamicSharedMemorySize,
                         ATTN_SMEM);
    attn_kernel<<<dim3(TT / 64, BB * HH), 256, ATTN_SMEM>>>(pQ, pK, pV, pC);

    gemm_kernel<<<gg, 256>>>(pC, wo, bo, out, 1.0f, 0);
}

// round 5
// speedup vs baseline: 2.2012x; 2.2012x over previous
#include <cuda_runtime.h>
#include <cuda_bf16.h>
#include <cstdint>

#define TT 2048
#define DD 512
#define MM 8192

// ---------------- scratch (device globals) ----------------------------------
__device__ __nv_bfloat16 g_xh[MM * DD], g_xl[MM * DD];
__device__ __nv_bfloat16 g_wqh[DD * DD], g_wql[DD * DD];
__device__ __nv_bfloat16 g_wkh[DD * DD], g_wkl[DD * DD];
__device__ __nv_bfloat16 g_wvh[DD * DD], g_wvl[DD * DD];
__device__ __nv_bfloat16 g_woh[DD * DD], g_wol[DD * DD];
__device__ __nv_bfloat16 g_Qh[32 * TT * 64], g_Ql[32 * TT * 64];
__device__ __nv_bfloat16 g_Kh[32 * TT * 64], g_Kl[32 * TT * 64];
__device__ __nv_bfloat16 g_Vh[32 * TT * 64], g_Vl[32 * TT * 64];
__device__ __nv_bfloat16 g_Ch[MM * DD], g_Cl[MM * DD];

// ---------------- helpers ----------------------------------------------------
__device__ __forceinline__ uint32_t smem_u32(const void* p) {
    uint32_t a;
    asm("{ .reg .u64 t; cvta.to.shared.u64 t, %1; cvt.u32.u64 %0, t; }"
        : "=r"(a) : "l"(p));
    return a;
}

#define SWZ(b) ((b) ^ (((b) >> 3) & 0x70))
__device__ __forceinline__ uint32_t swzV(uint32_t b) {
    return b ^ (((b >> 8) & 7) << 4);
}

#define LDSM4(R, addr)                                                         \
    asm volatile("ldmatrix.sync.aligned.m8n8.x4.shared.b16 {%0,%1,%2,%3}, [%4];" \
        : "=r"((R)[0]), "=r"((R)[1]), "=r"((R)[2]), "=r"((R)[3]) : "r"(addr))

#define MMA(C, A, b0, b1)                                                      \
    asm volatile("mma.sync.aligned.m16n8k16.row.col.f32.bf16.bf16.f32 "        \
        "{%0,%1,%2,%3}, {%4,%5,%6,%7}, {%8,%9}, {%0,%1,%2,%3};"                \
        : "+f"((C)[0]), "+f"((C)[1]), "+f"((C)[2]), "+f"((C)[3])               \
        : "r"((A)[0]), "r"((A)[1]), "r"((A)[2]), "r"((A)[3]), "r"(b0), "r"(b1))

__device__ __forceinline__ uint32_t pack2(float lo_e, float hi_e) {
    uint32_t r;
    asm("cvt.rn.bf16x2.f32 %0, %1, %2;" : "=r"(r) : "f"(hi_e), "f"(lo_e));
    return r;
}

// A-fragment ldmatrix address (tile rows 128B, SW128). regs a0..a3 order.
__device__ __forceinline__ uint32_t a_addr(uint32_t base, int m0, int k0, int lane) {
    int lr = (lane & 7) + (((lane >> 3) & 1) << 3);
    int lc = ((lane >> 4) & 1) << 3;
    return base + SWZ((uint32_t)((m0 + lr) * 128 + (k0 + lc) * 2));
}
// B-fragment ldmatrix address: regs = {b0,b1 of nfrag j; b0,b1 of nfrag j+1}
__device__ __forceinline__ uint32_t b_addr(uint32_t base, int n0, int k0, int lane) {
    int lr = (lane & 7) + (((lane >> 4) & 1) << 3);
    int lc = ((lane >> 3) & 1) << 3;
    return base + SWZ((uint32_t)((n0 + lr) * 128 + (k0 + lc) * 2));
}
// B-fragment from transposed-V tile (rows 256B)
__device__ __forceinline__ uint32_t v_addr(uint32_t base, int n0, int k0, int lane) {
    int lr = (lane & 7) + (((lane >> 4) & 1) << 3);
    int lc = ((lane >> 3) & 1) << 3;
    return base + swzV((uint32_t)((n0 + lr) * 256 + (k0 + lc) * 2));
}

// ---------------- fp32 -> bf16 hi/lo split -----------------------------------
__global__ void cvt_kernel(const float* __restrict__ src,
                           __nv_bfloat16* __restrict__ dh,
                           __nv_bfloat16* __restrict__ dl, int n) {
    for (int i = blockIdx.x * blockDim.x + threadIdx.x; i < n;
         i += gridDim.x * blockDim.x) {
        float v = src[i];
        __nv_bfloat16 h = __float2bfloat16(v);
        dh[i] = h;
        dl[i] = __float2bfloat16(v - __bfloat162float(h));
    }
}

// 128 rows x 64 bf16 (128B rows), SW128-swizzled
__device__ __forceinline__ void load_tile(char* dst, const __nv_bfloat16* src,
                                          int row_stride, int tid) {
#pragma unroll
    for (int i = tid; i < 1024; i += 256) {
        int row = i >> 3, seg = i & 7;
        uint4 v = *(const uint4*)(src + (size_t)row * row_stride + seg * 8);
        uint32_t b = row * 128 + seg * 16;
        *(uint4*)(dst + SWZ(b)) = v;
    }
}

// V tile transposed into [d=64][t=128] (256B rows). Lanes vary in t => no STS conflicts.
__device__ __forceinline__ void load_vt(char* dst, const __nv_bfloat16* src, int tid) {
    int tl = tid & 127;
    int s0 = tid >> 7;
#pragma unroll
    for (int kk = 0; kk < 4; kk++) {
        int seg = s0 + 2 * kk;
        uint4 v = *(const uint4*)(src + (size_t)tl * 64 + seg * 8);
        const unsigned short* us = (const unsigned short*)&v;
#pragma unroll
        for (int e = 0; e < 8; e++) {
            uint32_t b = (uint32_t)(seg * 8 + e) * 256 + tl * 2;
            *(unsigned short*)(dst + swzV(b)) = us[e];
        }
    }
}

// ---------------- GEMM: out = A @ W^T + bias (hi/lo 3-split) -----------------
#define G_AH 0
#define G_AL 16384
#define G_BH 32768
#define G_BL 49152
#define G_SMEM 65536

__global__ void __launch_bounds__(256)
gemm_mma(const __nv_bfloat16* __restrict__ Ah, const __nv_bfloat16* __restrict__ Al,
         const __nv_bfloat16* __restrict__ Bh, const __nv_bfloat16* __restrict__ Bl,
         const float* __restrict__ bias, float scale, int mode,
         float* __restrict__ outF,
         __nv_bfloat16* __restrict__ outH, __nv_bfloat16* __restrict__ outL)
{
    extern __shared__ char sm[];
    const uint32_t sb = smem_u32(sm);
    const int tid = threadIdx.x, lane = tid & 31, wid = tid >> 5;
    const int wm = wid >> 1, wn = wid & 1;
    const int m0w = wm * 32, n0w = wn * 64;
    const int m0 = blockIdx.x * 128, n0 = blockIdx.y * 128;

    float c[2][8][4];
#pragma unroll
    for (int a = 0; a < 2; a++)
#pragma unroll
        for (int b = 0; b < 8; b++)
#pragma unroll
            for (int d = 0; d < 4; d++) c[a][b][d] = 0.f;

    for (int ch = 0; ch < 8; ch++) {
        __syncthreads();
        load_tile(sm + G_AH, Ah + (size_t)m0 * DD + ch * 64, DD, tid);
        load_tile(sm + G_AL, Al + (size_t)m0 * DD + ch * 64, DD, tid);
        load_tile(sm + G_BH, Bh + (size_t)n0 * DD + ch * 64, DD, tid);
        load_tile(sm + G_BL, Bl + (size_t)n0 * DD + ch * 64, DD, tid);
        __syncthreads();
#pragma unroll
        for (int kf = 0; kf < 4; kf++) {
            uint32_t ah[2][4], al[2][4];
#pragma unroll
            for (int mi = 0; mi < 2; mi++) {
                LDSM4(ah[mi], a_addr(sb + G_AH, m0w + mi * 16, kf * 16, lane));
                LDSM4(al[mi], a_addr(sb + G_AL, m0w + mi * 16, kf * 16, lane));
            }
#pragma unroll
            for (int np = 0; np < 4; np++) {
                uint32_t bh4[4], bl4[4];
                LDSM4(bh4, b_addr(sb + G_BH, n0w + np * 16, kf * 16, lane));
                LDSM4(bl4, b_addr(sb + G_BL, n0w + np * 16, kf * 16, lane));
#pragma unroll
                for (int mi = 0; mi < 2; mi++) {
                    MMA(c[mi][2 * np],     ah[mi], bh4[0], bh4[1]);
                    MMA(c[mi][2 * np + 1], ah[mi], bh4[2], bh4[3]);
                    MMA(c[mi][2 * np],     ah[mi], bl4[0], bl4[1]);
                    MMA(c[mi][2 * np + 1], ah[mi], bl4[2], bl4[3]);
                    MMA(c[mi][2 * np],     al[mi], bh4[0], bh4[1]);
                    MMA(c[mi][2 * np + 1], al[mi], bh4[2], bh4[3]);
                }
            }
        }
    }

    const int gid = lane >> 2, tig = lane & 3;
#pragma unroll
    for (int mi = 0; mi < 2; mi++)
#pragma unroll
    for (int rh = 0; rh < 2; rh++) {
        int m = m0 + m0w + mi * 16 + rh * 8 + gid;
        if (mode == 0) {
            float* dst = outF + (size_t)m * DD + n0 + n0w;
#pragma unroll
            for (int j = 0; j < 8; j++) {
                int col = 8 * j + tig * 2;
                float v0 = c[mi][j][rh * 2 + 0] + bias[n0 + n0w + col];
                float v1 = c[mi][j][rh * 2 + 1] + bias[n0 + n0w + col + 1];
                *(float2*)(dst + col) = make_float2(v0, v1);
            }
        } else {
            int head = blockIdx.y * 2 + wn;
            int b = m >> 11, t = m & 2047;
            size_t base = ((size_t)(b * 8 + head) * TT + t) * 64;
#pragma unroll
            for (int j = 0; j < 8; j++) {
                int d = 8 * j + tig * 2;
                float v0 = (c[mi][j][rh * 2 + 0] + bias[(head << 6) + d]) * scale;
                float v1 = (c[mi][j][rh * 2 + 1] + bias[(head << 6) + d + 1]) * scale;
                uint32_t h2 = pack2(v0, v1);
                float f0 = __uint_as_float(h2 << 16);
                float f1 = __uint_as_float(h2 & 0xffff0000u);
                uint32_t l2 = pack2(v0 - f0, v1 - f1);
                *(uint32_t*)(outH + base + d) = h2;
                *(uint32_t*)(outL + base + d) = l2;
            }
        }
    }
}

// ---------------- flash attention (mma.sync) ---------------------------------
#define A_QH 0
#define A_QL 16384
#define A_KH 32768
#define A_KL 49152
#define A_VH 65536
#define A_VL 81920
#define A_SMEM 98304

__global__ void __launch_bounds__(256)
attn_mma(const __nv_bfloat16* __restrict__ Qh, const __nv_bfloat16* __restrict__ Ql,
         const __nv_bfloat16* __restrict__ Kh, const __nv_bfloat16* __restrict__ Kl,
         const __nv_bfloat16* __restrict__ Vh, const __nv_bfloat16* __restrict__ Vl,
         __nv_bfloat16* __restrict__ Ch, __nv_bfloat16* __restrict__ Cl)
{
    extern __shared__ char sm[];
    const uint32_t sb = smem_u32(sm);
    const int tid = threadIdx.x, lane = tid & 31, wid = tid >> 5;
    const int m0w = wid * 16;
    const int qt = blockIdx.x, bh = blockIdx.y;
    const size_t hb = (size_t)bh * TT;
    const int gid = lane >> 2, tig = lane & 3;

    load_tile(sm + A_QH, Qh + (hb + qt * 128) * 64, 64, tid);
    load_tile(sm + A_QL, Ql + (hb + qt * 128) * 64, 64, tid);
    __syncthreads();

    uint32_t qh4[4][4], ql4[4][4];
#pragma unroll
    for (int kf = 0; kf < 4; kf++) {
        LDSM4(qh4[kf], a_addr(sb + A_QH, m0w, kf * 16, lane));
        LDSM4(ql4[kf], a_addr(sb + A_QL, m0w, kf * 16, lane));
    }

    float o[8][4];
#pragma unroll
    for (int j = 0; j < 8; j++)
#pragma unroll
        for (int d = 0; d < 4; d++) o[j][d] = 0.f;
    float mrow[2] = {-1e30f, -1e30f}, lrow[2] = {0.f, 0.f};

    for (int kt = 0; kt < 16; kt++) {
        __syncthreads();
        load_tile(sm + A_KH, Kh + (hb + kt * 128) * 64, 64, tid);
        load_tile(sm + A_KL, Kl + (hb + kt * 128) * 64, 64, tid);
        load_vt(sm + A_VH, Vh + (hb + kt * 128) * 64, tid);
        load_vt(sm + A_VL, Vl + (hb + kt * 128) * 64, tid);
        __syncthreads();

        float sa[16][4];
#pragma unroll
        for (int j = 0; j < 16; j++)
#pragma unroll
            for (int d = 0; d < 4; d++) sa[j][d] = 0.f;

#pragma unroll
        for (int kf = 0; kf < 4; kf++) {
#pragma unroll
            for (int np = 0; np < 8; np++) {
                uint32_t b4[4], bl4[4];
                LDSM4(b4,  b_addr(sb + A_KH, np * 16, kf * 16, lane));
                LDSM4(bl4, b_addr(sb + A_KL, np * 16, kf * 16, lane));
                MMA(sa[2 * np],     qh4[kf], b4[0], b4[1]);
                MMA(sa[2 * np + 1], qh4[kf], b4[2], b4[3]);
                MMA(sa[2 * np],     qh4[kf], bl4[0], bl4[1]);
                MMA(sa[2 * np + 1], qh4[kf], bl4[2], bl4[3]);
                MMA(sa[2 * np],     ql4[kf], b4[0], b4[1]);
                MMA(sa[2 * np + 1], ql4[kf], b4[2], b4[3]);
            }
        }

        // online softmax on 2 rows per thread (rows gid, gid+8)
#pragma unroll
        for (int rh = 0; rh < 2; rh++) {
            float mx = -1e30f;
#pragma unroll
            for (int j = 0; j < 16; j++)
                mx = fmaxf(mx, fmaxf(sa[j][rh * 2], sa[j][rh * 2 + 1]));
            mx = fmaxf(mx, __shfl_xor_sync(0xffffffffu, mx, 1));
            mx = fmaxf(mx, __shfl_xor_sync(0xffffffffu, mx, 2));
            float mnew = fmaxf(mrow[rh], mx);
            float corr = __expf(mrow[rh] - mnew);
            float ps = 0.f;
#pragma unroll
            for (int j = 0; j < 16; j++) {
                float e0 = __expf(sa[j][rh * 2] - mnew);
                float e1 = __expf(sa[j][rh * 2 + 1] - mnew);
                sa[j][rh * 2] = e0;
                sa[j][rh * 2 + 1] = e1;
                ps += e0 + e1;
            }
            ps += __shfl_xor_sync(0xffffffffu, ps, 1);
            ps += __shfl_xor_sync(0xffffffffu, ps, 2);
            lrow[rh] = lrow[rh] * corr + ps;
            mrow[rh] = mnew;
#pragma unroll
            for (int j = 0; j < 8; j++) {
                o[j][rh * 2] *= corr;
                o[j][rh * 2 + 1] *= corr;
            }
        }

        // O += P * V  (P fragments built from registers)
#pragma unroll
        for (int kf = 0; kf < 8; kf++) {
            uint32_t pah[4], pal[4];
#pragma unroll
            for (int q = 0; q < 4; q++) {
                const float* src = (q < 2) ? sa[2 * kf] : sa[2 * kf + 1];
                float p0 = src[(q & 1) * 2], p1 = src[(q & 1) * 2 + 1];
                uint32_t h2 = pack2(p0, p1);
                float f0 = __uint_as_float(h2 << 16);
                float f1 = __uint_as_float(h2 & 0xffff0000u);
                pah[q] = h2;
                pal[q] = pack2(p0 - f0, p1 - f1);
            }
#pragma unroll
            for (int np = 0; np < 4; np++) {
                uint32_t vh4[4], vl4[4];
                LDSM4(vh4, v_addr(sb + A_VH, np * 16, kf * 16, lane));
                LDSM4(vl4, v_addr(sb + A_VL, np * 16, kf * 16, lane));
                MMA(o[2 * np],     pah, vh4[0], vh4[1]);
                MMA(o[2 * np + 1], pah, vh4[2], vh4[3]);
                MMA(o[2 * np],     pah, vl4[0], vl4[1]);
                MMA(o[2 * np + 1], pah, vl4[2], vl4[3]);
                MMA(o[2 * np],     pal, vh4[0], vh4[1]);
                MMA(o[2 * np + 1], pal, vh4[2], vh4[3]);
            }
        }
    }

    const int b = bh >> 3, h = bh & 7;
#pragma unroll
    for (int rh = 0; rh < 2; rh++) {
        float inv = 1.f / lrow[rh];
        int t = qt * 128 + m0w + rh * 8 + gid;
        size_t base = ((size_t)(b * TT + t)) * DD + h * 64;
#pragma unroll
        for (int j = 0; j < 8; j++) {
            int d = 8 * j + tig * 2;
            float v0 = o[j][rh * 2] * inv;
            float v1 = o[j][rh * 2 + 1] * inv;
            uint32_t h2 = pack2(v0, v1);
            float f0 = __uint_as_float(h2 << 16);
            float f1 = __uint_as_float(h2 & 0xffff0000u);
            uint32_t l2 = pack2(v0 - f0, v1 - f1);
            *(uint32_t*)(Ch + base + d) = h2;
            *(uint32_t*)(Cl + base + d) = l2;
        }
    }
}

// ---------------------------------------------------------------------------
extern "C" void kernel_launch(void* const* d_in, const int* in_sizes, int n_in,
                              void* d_out, int out_size)
{
    const float* x  = (const float*)d_in[0];
    const float* wq = (const float*)d_in[1];
    const float* bq = (const float*)d_in[2];
    const float* wk = (const float*)d_in[3];
    const float* bk = (const float*)d_in[4];
    const float* wv = (const float*)d_in[5];
    const float* bv = (const float*)d_in[6];
    const float* wo = (const float*)d_in[7];
    const float* bo = (const float*)d_in[8];
    float* out = (float*)d_out;

    __nv_bfloat16 *xh, *xl, *wqh, *wql, *wkh, *wkl, *wvh, *wvl, *woh, *wol;
    __nv_bfloat16 *qh, *ql, *kh, *kl, *vh, *vl, *ch, *cl;
    cudaGetSymbolAddress((void**)&xh, g_xh);   cudaGetSymbolAddress((void**)&xl, g_xl);
    cudaGetSymbolAddress((void**)&wqh, g_wqh); cudaGetSymbolAddress((void**)&wql, g_wql);
    cudaGetSymbolAddress((void**)&wkh, g_wkh); cudaGetSymbolAddress((void**)&wkl, g_wkl);
    cudaGetSymbolAddress((void**)&wvh, g_wvh); cudaGetSymbolAddress((void**)&wvl, g_wvl);
    cudaGetSymbolAddress((void**)&woh, g_woh); cudaGetSymbolAddress((void**)&wol, g_wol);
    cudaGetSymbolAddress((void**)&qh, g_Qh);   cudaGetSymbolAddress((void**)&ql, g_Ql);
    cudaGetSymbolAddress((void**)&kh, g_Kh);   cudaGetSymbolAddress((void**)&kl, g_Kl);
    cudaGetSymbolAddress((void**)&vh, g_Vh);   cudaGetSymbolAddress((void**)&vl, g_Vl);
    cudaGetSymbolAddress((void**)&ch, g_Ch);   cudaGetSymbolAddress((void**)&cl, g_Cl);

    cvt_kernel<<<512, 256>>>(x, xh, xl, MM * DD);
    cvt_kernel<<<128, 256>>>(wq, wqh, wql, DD * DD);
    cvt_kernel<<<128, 256>>>(wk, wkh, wkl, DD * DD);
    cvt_kernel<<<128, 256>>>(wv, wvh, wvl, DD * DD);
    cvt_kernel<<<128, 256>>>(wo, woh, wol, DD * DD);

    cudaFuncSetAttribute(gemm_mma, cudaFuncAttributeMaxDynamicSharedMemorySize, G_SMEM);
    cudaFuncSetAttribute(attn_mma, cudaFuncAttributeMaxDynamicSharedMemorySize, A_SMEM);

    dim3 gg(MM / 128, DD / 128);
    gemm_mma<<<gg, 256, G_SMEM>>>(xh, xl, wqh, wql, bq, 0.125f, 1, nullptr, qh, ql);
    gemm_mma<<<gg, 256, G_SMEM>>>(xh, xl, wkh, wkl, bk, 1.0f,   1, nullptr, kh, kl);
    gemm_mma<<<gg, 256, G_SMEM>>>(xh, xl, wvh, wvl, bv, 1.0f,   1, nullptr, vh, vl);

    attn_mma<<<dim3(TT / 128, 32), 256, A_SMEM>>>(qh, ql, kh, kl, vh, vl, ch, cl);

    gemm_mma<<<gg, 256, G_SMEM>>>(ch, cl, woh, wol, bo, 1.0f, 0, out, nullptr, nullptr);
}

// round 6
// speedup vs baseline: 2.8705x; 1.3040x over previous
#include <cuda_runtime.h>
#include <cuda_bf16.h>
#include <cstdint>

#define TT 2048
#define DD 512
#define MM 8192

// ---------------- scratch (device globals) ----------------------------------
__device__ __nv_bfloat16 g_xh[MM * DD], g_xl[MM * DD];
__device__ __nv_bfloat16 g_wqh[DD * DD], g_wql[DD * DD];
__device__ __nv_bfloat16 g_wkh[DD * DD], g_wkl[DD * DD];
__device__ __nv_bfloat16 g_wvh[DD * DD], g_wvl[DD * DD];
__device__ __nv_bfloat16 g_woh[DD * DD], g_wol[DD * DD];
__device__ __nv_bfloat16 g_Qh[32 * TT * 64], g_Ql[32 * TT * 64];
__device__ __nv_bfloat16 g_Kh[32 * TT * 64], g_Kl[32 * TT * 64];
__device__ __nv_bfloat16 g_Vth[32 * 64 * TT], g_Vtl[32 * 64 * TT]; // [bh][d][t]
__device__ __nv_bfloat16 g_Ch[MM * DD], g_Cl[MM * DD];

// ---------------- helpers ----------------------------------------------------
__device__ __forceinline__ uint32_t smem_u32(const void* p) {
    uint32_t a;
    asm("{ .reg .u64 t; cvta.to.shared.u64 t, %1; cvt.u32.u64 %0, t; }"
        : "=r"(a) : "l"(p));
    return a;
}

#define SWZ(b) ((b) ^ (((b) >> 3) & 0x70))
__device__ __forceinline__ uint32_t swzV(uint32_t b) {
    return b ^ (((b >> 8) & 7) << 4);
}

#define CP16(d, s) asm volatile("cp.async.cg.shared.global [%0], [%1], 16;" :: "r"(d), "l"(s))
#define CPC()      asm volatile("cp.async.commit_group;" ::: "memory")
#define CPW(n)     asm volatile("cp.async.wait_group %0;" :: "n"(n) : "memory")

#define LDSM4(R, addr)                                                         \
    asm volatile("ldmatrix.sync.aligned.m8n8.x4.shared.b16 {%0,%1,%2,%3}, [%4];" \
        : "=r"((R)[0]), "=r"((R)[1]), "=r"((R)[2]), "=r"((R)[3]) : "r"(addr))

#define MMA(C, A, b0, b1)                                                      \
    asm volatile("mma.sync.aligned.m16n8k16.row.col.f32.bf16.bf16.f32 "        \
        "{%0,%1,%2,%3}, {%4,%5,%6,%7}, {%8,%9}, {%0,%1,%2,%3};"                \
        : "+f"((C)[0]), "+f"((C)[1]), "+f"((C)[2]), "+f"((C)[3])               \
        : "r"((A)[0]), "r"((A)[1]), "r"((A)[2]), "r"((A)[3]), "r"(b0), "r"(b1))

__device__ __forceinline__ uint32_t pack2(float lo_e, float hi_e) {
    uint32_t r;
    asm("cvt.rn.bf16x2.f32 %0, %1, %2;" : "=r"(r) : "f"(hi_e), "f"(lo_e));
    return r;
}

__device__ __forceinline__ uint32_t a_addr(uint32_t base, int m0, int k0, int lane) {
    int lr = (lane & 7) + (((lane >> 3) & 1) << 3);
    int lc = ((lane >> 4) & 1) << 3;
    return base + SWZ((uint32_t)((m0 + lr) * 128 + (k0 + lc) * 2));
}
__device__ __forceinline__ uint32_t b_addr(uint32_t base, int n0, int k0, int lane) {
    int lr = (lane & 7) + (((lane >> 4) & 1) << 3);
    int lc = ((lane >> 3) & 1) << 3;
    return base + SWZ((uint32_t)((n0 + lr) * 128 + (k0 + lc) * 2));
}
__device__ __forceinline__ uint32_t v_addr(uint32_t base, int n0, int k0, int lane) {
    int lr = (lane & 7) + (((lane >> 4) & 1) << 3);
    int lc = ((lane >> 3) & 1) << 3;
    return base + swzV((uint32_t)((n0 + lr) * 256 + (k0 + lc) * 2));
}

// ---------------- fp32 -> bf16 hi/lo split (vectorized) ----------------------
__device__ __forceinline__ void cvt4_one(const float4* __restrict__ src,
                                         uint2* __restrict__ dh,
                                         uint2* __restrict__ dl, int i) {
    float4 v = src[i];
    uint32_t h01 = pack2(v.x, v.y);
    uint32_t h23 = pack2(v.z, v.w);
    float r0 = v.x - __uint_as_float(h01 << 16);
    float r1 = v.y - __uint_as_float(h01 & 0xffff0000u);
    float r2 = v.z - __uint_as_float(h23 << 16);
    float r3 = v.w - __uint_as_float(h23 & 0xffff0000u);
    dh[i] = make_uint2(h01, h23);
    dl[i] = make_uint2(pack2(r0, r1), pack2(r2, r3));
}

__global__ void cvt_x(const float* __restrict__ src,
                      __nv_bfloat16* __restrict__ dh,
                      __nv_bfloat16* __restrict__ dl, int n4) {
    for (int i = blockIdx.x * blockDim.x + threadIdx.x; i < n4;
         i += gridDim.x * blockDim.x)
        cvt4_one((const float4*)src, (uint2*)dh, (uint2*)dl, i);
}

__global__ void cvt_w(const float* s0, const float* s1, const float* s2, const float* s3,
                      __nv_bfloat16* h0, __nv_bfloat16* l0,
                      __nv_bfloat16* h1, __nv_bfloat16* l1,
                      __nv_bfloat16* h2, __nv_bfloat16* l2,
                      __nv_bfloat16* h3, __nv_bfloat16* l3) {
    const float* s; __nv_bfloat16 *h, *l;
    switch (blockIdx.y) {
        case 0:  s = s0; h = h0; l = l0; break;
        case 1:  s = s1; h = h1; l = l1; break;
        case 2:  s = s2; h = h2; l = l2; break;
        default: s = s3; h = h3; l = l3; break;
    }
    const int n4 = DD * DD / 4;
    for (int i = blockIdx.x * blockDim.x + threadIdx.x; i < n4;
         i += gridDim.x * blockDim.x)
        cvt4_one((const float4*)s, (uint2*)h, (uint2*)l, i);
}

// ---------------- cp.async tile loaders --------------------------------------
// 128 rows x 64 bf16 (128B rows), SW128
__device__ __forceinline__ void cp_tile(uint32_t dst, const __nv_bfloat16* src,
                                        int row_stride, int tid) {
#pragma unroll
    for (int i = tid; i < 1024; i += 256) {
        int row = i >> 3, seg = i & 7;
        CP16(dst + SWZ((uint32_t)(row * 128 + seg * 16)),
             src + (size_t)row * row_stride + seg * 8);
    }
}
// 64 rows x 128 bf16 (256B rows), swzV  (V^T tile)
__device__ __forceinline__ void cp_vtile(uint32_t dst, const __nv_bfloat16* src,
                                         int tid) {
#pragma unroll
    for (int i = tid; i < 1024; i += 256) {
        int row = i >> 4, seg = i & 15;
        CP16(dst + swzV((uint32_t)(row * 256 + seg * 16)),
             src + (size_t)row * TT + seg * 8);
    }
}

// ---------------- GEMM: out = A @ W^T + bias (hi/lo 3-split) -----------------
// mode 0: fp32 [M,512]; mode 1: per-head hi/lo [bh][t][64]; mode 2: V^T [bh][d][t]
#define G_AH 0
#define G_AL 16384
#define G_BH 32768
#define G_BL 49152
#define G_SMEM 65536

__global__ void __launch_bounds__(256)
gemm_mma(const __nv_bfloat16* __restrict__ Ah, const __nv_bfloat16* __restrict__ Al,
         const __nv_bfloat16* __restrict__ Bh, const __nv_bfloat16* __restrict__ Bl,
         const float* __restrict__ bias, float scale, int mode,
         float* __restrict__ outF,
         __nv_bfloat16* __restrict__ outH, __nv_bfloat16* __restrict__ outL)
{
    extern __shared__ char sm[];
    const uint32_t sb = smem_u32(sm);
    const int tid = threadIdx.x, lane = tid & 31, wid = tid >> 5;
    const int wm = wid >> 1, wn = wid & 1;
    const int m0w = wm * 32, n0w = wn * 64;
    const int m0 = blockIdx.x * 128, n0 = blockIdx.y * 128;

    float c[2][8][4];
#pragma unroll
    for (int a = 0; a < 2; a++)
#pragma unroll
        for (int b = 0; b < 8; b++)
#pragma unroll
            for (int d = 0; d < 4; d++) c[a][b][d] = 0.f;

    for (int ch = 0; ch < 8; ch++) {
        cp_tile(sb + G_AH, Ah + (size_t)m0 * DD + ch * 64, DD, tid);
        cp_tile(sb + G_AL, Al + (size_t)m0 * DD + ch * 64, DD, tid);
        cp_tile(sb + G_BH, Bh + (size_t)n0 * DD + ch * 64, DD, tid);
        cp_tile(sb + G_BL, Bl + (size_t)n0 * DD + ch * 64, DD, tid);
        CPC();
        CPW(0);
        __syncthreads();
#pragma unroll
        for (int kf = 0; kf < 4; kf++) {
            uint32_t ah[2][4], al[2][4];
#pragma unroll
            for (int mi = 0; mi < 2; mi++) {
                LDSM4(ah[mi], a_addr(sb + G_AH, m0w + mi * 16, kf * 16, lane));
                LDSM4(al[mi], a_addr(sb + G_AL, m0w + mi * 16, kf * 16, lane));
            }
#pragma unroll
            for (int np = 0; np < 4; np++) {
                uint32_t bh4[4], bl4[4];
                LDSM4(bh4, b_addr(sb + G_BH, n0w + np * 16, kf * 16, lane));
                LDSM4(bl4, b_addr(sb + G_BL, n0w + np * 16, kf * 16, lane));
#pragma unroll
                for (int mi = 0; mi < 2; mi++) {
                    MMA(c[mi][2 * np],     ah[mi], bh4[0], bh4[1]);
                    MMA(c[mi][2 * np + 1], ah[mi], bh4[2], bh4[3]);
                    MMA(c[mi][2 * np],     ah[mi], bl4[0], bl4[1]);
                    MMA(c[mi][2 * np + 1], ah[mi], bl4[2], bl4[3]);
                    MMA(c[mi][2 * np],     al[mi], bh4[0], bh4[1]);
                    MMA(c[mi][2 * np + 1], al[mi], bh4[2], bh4[3]);
                }
            }
        }
        __syncthreads();
    }

    const int gid = lane >> 2, tig = lane & 3;
#pragma unroll
    for (int mi = 0; mi < 2; mi++)
#pragma unroll
    for (int rh = 0; rh < 2; rh++) {
        int m = m0 + m0w + mi * 16 + rh * 8 + gid;
        if (mode == 0) {
            float* dst = outF + (size_t)m * DD + n0 + n0w;
#pragma unroll
            for (int j = 0; j < 8; j++) {
                int col = 8 * j + tig * 2;
                float v0 = c[mi][j][rh * 2 + 0] + bias[n0 + n0w + col];
                float v1 = c[mi][j][rh * 2 + 1] + bias[n0 + n0w + col + 1];
                *(float2*)(dst + col) = make_float2(v0, v1);
            }
        } else if (mode == 1) {
            int head = blockIdx.y * 2 + wn;
            int b = m >> 11, t = m & 2047;
            size_t base = ((size_t)(b * 8 + head) * TT + t) * 64;
#pragma unroll
            for (int j = 0; j < 8; j++) {
                int d = 8 * j + tig * 2;
                float v0 = (c[mi][j][rh * 2 + 0] + bias[(head << 6) + d]) * scale;
                float v1 = (c[mi][j][rh * 2 + 1] + bias[(head << 6) + d + 1]) * scale;
                uint32_t h2 = pack2(v0, v1);
                float f0 = __uint_as_float(h2 << 16);
                float f1 = __uint_as_float(h2 & 0xffff0000u);
                uint32_t l2 = pack2(v0 - f0, v1 - f1);
                *(uint32_t*)(outH + base + d) = h2;
                *(uint32_t*)(outL + base + d) = l2;
            }
        } else {
            // V^T: [bh][d][t]
            int head = blockIdx.y * 2 + wn;
            int b = m >> 11, t = m & 2047;
            size_t vb = (size_t)(b * 8 + head) * 64 * TT;
#pragma unroll
            for (int j = 0; j < 8; j++) {
                int d = 8 * j + tig * 2;
#pragma unroll
                for (int e = 0; e < 2; e++) {
                    float v = c[mi][j][rh * 2 + e] + bias[(head << 6) + d + e];
                    __nv_bfloat16 h = __float2bfloat16(v);
                    __nv_bfloat16 l = __float2bfloat16(v - __bfloat162float(h));
                    outH[vb + (size_t)(d + e) * TT + t] = h;
                    outL[vb + (size_t)(d + e) * TT + t] = l;
                }
            }
        }
    }
}

// ---------------- flash attention (mma.sync, cp.async double-buffered) -------
#define A_QH 0
#define A_QL 16384
#define A_ST 32768
#define A_STSZ 65536
#define A_KH 0
#define A_KL 16384
#define A_VH 32768
#define A_VL 49152
#define A_SMEM 163840

__global__ void __launch_bounds__(256)
attn_mma(const __nv_bfloat16* __restrict__ Qh, const __nv_bfloat16* __restrict__ Ql,
         const __nv_bfloat16* __restrict__ Kh, const __nv_bfloat16* __restrict__ Kl,
         const __nv_bfloat16* __restrict__ Vth, const __nv_bfloat16* __restrict__ Vtl,
         __nv_bfloat16* __restrict__ Ch, __nv_bfloat16* __restrict__ Cl)
{
    extern __shared__ char sm[];
    const uint32_t sb = smem_u32(sm);
    const int tid = threadIdx.x, lane = tid & 31, wid = tid >> 5;
    const int m0w = wid * 16;
    const int qt = blockIdx.x, bh = blockIdx.y;
    const size_t hb = (size_t)bh * TT;
    const int gid = lane >> 2, tig = lane & 3;

    // prologue: Q group, then kt=0 stage group
    cp_tile(sb + A_QH, Qh + (hb + qt * 128) * 64, 64, tid);
    cp_tile(sb + A_QL, Ql + (hb + qt * 128) * 64, 64, tid);
    CPC();
    {
        uint32_t s0 = sb + A_ST;
        cp_tile(s0 + A_KH, Kh + hb * 64, 64, tid);
        cp_tile(s0 + A_KL, Kl + hb * 64, 64, tid);
        cp_vtile(s0 + A_VH, Vth + hb * 64, tid);
        cp_vtile(s0 + A_VL, Vtl + hb * 64, tid);
        CPC();
    }
    CPW(1);
    __syncthreads();

    uint32_t qh4[4][4], ql4[4][4];
#pragma unroll
    for (int kf = 0; kf < 4; kf++) {
        LDSM4(qh4[kf], a_addr(sb + A_QH, m0w, kf * 16, lane));
        LDSM4(ql4[kf], a_addr(sb + A_QL, m0w, kf * 16, lane));
    }

    float o[8][4];
#pragma unroll
    for (int j = 0; j < 8; j++)
#pragma unroll
        for (int d = 0; d < 4; d++) o[j][d] = 0.f;
    float mrow[2] = {-1e30f, -1e30f}, lrow[2] = {0.f, 0.f};

    for (int kt = 0; kt < 16; kt++) {
        if (kt < 15) {
            uint32_t sn = sb + A_ST + ((kt + 1) & 1) * A_STSZ;
            cp_tile(sn + A_KH, Kh + (hb + (kt + 1) * 128) * 64, 64, tid);
            cp_tile(sn + A_KL, Kl + (hb + (kt + 1) * 128) * 64, 64, tid);
            cp_vtile(sn + A_VH, Vth + hb * 64 + (kt + 1) * 128, tid);
            cp_vtile(sn + A_VL, Vtl + hb * 64 + (kt + 1) * 128, tid);
            CPC();
            CPW(1);
        } else {
            CPW(0);
        }
        __syncthreads();
        const uint32_t sc = sb + A_ST + (kt & 1) * A_STSZ;

        float sa[16][4];
#pragma unroll
        for (int j = 0; j < 16; j++)
#pragma unroll
            for (int d = 0; d < 4; d++) sa[j][d] = 0.f;

#pragma unroll
        for (int kf = 0; kf < 4; kf++) {
#pragma unroll
            for (int np = 0; np < 8; np++) {
                uint32_t b4[4], bl4[4];
                LDSM4(b4,  b_addr(sc + A_KH, np * 16, kf * 16, lane));
                LDSM4(bl4, b_addr(sc + A_KL, np * 16, kf * 16, lane));
                MMA(sa[2 * np],     qh4[kf], b4[0], b4[1]);
                MMA(sa[2 * np + 1], qh4[kf], b4[2], b4[3]);
                MMA(sa[2 * np],     qh4[kf], bl4[0], bl4[1]);
                MMA(sa[2 * np + 1], qh4[kf], bl4[2], bl4[3]);
                MMA(sa[2 * np],     ql4[kf], b4[0], b4[1]);
                MMA(sa[2 * np + 1], ql4[kf], b4[2], b4[3]);
            }
        }

        // online softmax on 2 rows per thread
#pragma unroll
        for (int rh = 0; rh < 2; rh++) {
            float mx = -1e30f;
#pragma unroll
            for (int j = 0; j < 16; j++)
                mx = fmaxf(mx, fmaxf(sa[j][rh * 2], sa[j][rh * 2 + 1]));
            mx = fmaxf(mx, __shfl_xor_sync(0xffffffffu, mx, 1));
            mx = fmaxf(mx, __shfl_xor_sync(0xffffffffu, mx, 2));
            float mnew = fmaxf(mrow[rh], mx);
            float corr = __expf(mrow[rh] - mnew);
            float ps = 0.f;
#pragma unroll
            for (int j = 0; j < 16; j++) {
                float e0 = __expf(sa[j][rh * 2] - mnew);
                float e1 = __expf(sa[j][rh * 2 + 1] - mnew);
                sa[j][rh * 2] = e0;
                sa[j][rh * 2 + 1] = e1;
                ps += e0 + e1;
            }
            ps += __shfl_xor_sync(0xffffffffu, ps, 1);
            ps += __shfl_xor_sync(0xffffffffu, ps, 2);
            lrow[rh] = lrow[rh] * corr + ps;
            mrow[rh] = mnew;
#pragma unroll
            for (int j = 0; j < 8; j++) {
                o[j][rh * 2] *= corr;
                o[j][rh * 2 + 1] *= corr;
            }
        }

        // O += P * V
#pragma unroll
        for (int kf = 0; kf < 8; kf++) {
            uint32_t pah[4], pal[4];
#pragma unroll
            for (int q = 0; q < 4; q++) {
                const float* src = (q < 2) ? sa[2 * kf] : sa[2 * kf + 1];
                float p0 = src[(q & 1) * 2], p1 = src[(q & 1) * 2 + 1];
                uint32_t h2 = pack2(p0, p1);
                float f0 = __uint_as_float(h2 << 16);
                float f1 = __uint_as_float(h2 & 0xffff0000u);
                pah[q] = h2;
                pal[q] = pack2(p0 - f0, p1 - f1);
            }
#pragma unroll
            for (int np = 0; np < 4; np++) {
                uint32_t vh4[4], vl4[4];
                LDSM4(vh4, v_addr(sc + A_VH, np * 16, kf * 16, lane));
                LDSM4(vl4, v_addr(sc + A_VL, np * 16, kf * 16, lane));
                MMA(o[2 * np],     pah, vh4[0], vh4[1]);
                MMA(o[2 * np + 1], pah, vh4[2], vh4[3]);
                MMA(o[2 * np],     pah, vl4[0], vl4[1]);
                MMA(o[2 * np + 1], pah, vl4[2], vl4[3]);
                MMA(o[2 * np],     pal, vh4[0], vh4[1]);
                MMA(o[2 * np + 1], pal, vh4[2], vh4[3]);
            }
        }
        __syncthreads();
    }

    const int b = bh >> 3, h = bh & 7;
#pragma unroll
    for (int rh = 0; rh < 2; rh++) {
        float inv = 1.f / lrow[rh];
        int t = qt * 128 + m0w + rh * 8 + gid;
        size_t base = ((size_t)(b * TT + t)) * DD + h * 64;
#pragma unroll
        for (int j = 0; j < 8; j++) {
            int d = 8 * j + tig * 2;
            float v0 = o[j][rh * 2] * inv;
            float v1 = o[j][rh * 2 + 1] * inv;
            uint32_t h2 = pack2(v0, v1);
            float f0 = __uint_as_float(h2 << 16);
            float f1 = __uint_as_float(h2 & 0xffff0000u);
            uint32_t l2 = pack2(v0 - f0, v1 - f1);
            *(uint32_t*)(Ch + base + d) = h2;
            *(uint32_t*)(Cl + base + d) = l2;
        }
    }
}

// ---------------------------------------------------------------------------
extern "C" void kernel_launch(void* const* d_in, const int* in_sizes, int n_in,
                              void* d_out, int out_size)
{
    const float* x  = (const float*)d_in[0];
    const float* wq = (const float*)d_in[1];
    const float* bq = (const float*)d_in[2];
    const float* wk = (const float*)d_in[3];
    const float* bk = (const float*)d_in[4];
    const float* wv = (const float*)d_in[5];
    const float* bv = (const float*)d_in[6];
    const float* wo = (const float*)d_in[7];
    const float* bo = (const float*)d_in[8];
    float* out = (float*)d_out;

    __nv_bfloat16 *xh, *xl, *wqh, *wql, *wkh, *wkl, *wvh, *wvl, *woh, *wol;
    __nv_bfloat16 *qh, *ql, *kh, *kl, *vth, *vtl, *ch, *cl;
    cudaGetSymbolAddress((void**)&xh, g_xh);   cudaGetSymbolAddress((void**)&xl, g_xl);
    cudaGetSymbolAddress((void**)&wqh, g_wqh); cudaGetSymbolAddress((void**)&wql, g_wql);
    cudaGetSymbolAddress((void**)&wkh, g_wkh); cudaGetSymbolAddress((void**)&wkl, g_wkl);
    cudaGetSymbolAddress((void**)&wvh, g_wvh); cudaGetSymbolAddress((void**)&wvl, g_wvl);
    cudaGetSymbolAddress((void**)&woh, g_woh); cudaGetSymbolAddress((void**)&wol, g_wol);
    cudaGetSymbolAddress((void**)&qh, g_Qh);   cudaGetSymbolAddress((void**)&ql, g_Ql);
    cudaGetSymbolAddress((void**)&kh, g_Kh);   cudaGetSymbolAddress((void**)&kl, g_Kl);
    cudaGetSymbolAddress((void**)&vth, g_Vth); cudaGetSymbolAddress((void**)&vtl, g_Vtl);
    cudaGetSymbolAddress((void**)&ch, g_Ch);   cudaGetSymbolAddress((void**)&cl, g_Cl);

    cvt_x<<<512, 256>>>(x, xh, xl, MM * DD / 4);
    cvt_w<<<dim3(64, 4), 256>>>(wq, wk, wv, wo, wqh, wql, wkh, wkl,
                                wvh, wvl, woh, wol);

    cudaFuncSetAttribute(gemm_mma, cudaFuncAttributeMaxDynamicSharedMemorySize, G_SMEM);
    cudaFuncSetAttribute(attn_mma, cudaFuncAttributeMaxDynamicSharedMemorySize, A_SMEM);

    dim3 gg(MM / 128, DD / 128);
    gemm_mma<<<gg, 256, G_SMEM>>>(xh, xl, wqh, wql, bq, 0.125f, 1, nullptr, qh, ql);
    gemm_mma<<<gg, 256, G_SMEM>>>(xh, xl, wkh, wkl, bk, 1.0f,   1, nullptr, kh, kl);
    gemm_mma<<<gg, 256, G_SMEM>>>(xh, xl, wvh, wvl, bv, 1.0f,   2, nullptr, vth, vtl);

    attn_mma<<<dim3(TT / 128, 32), 256, A_SMEM>>>(qh, ql, kh, kl, vth, vtl, ch, cl);

    gemm_mma<<<gg, 256, G_SMEM>>>(ch, cl, woh, wol, bo, 1.0f, 0, out, nullptr, nullptr);
}

// round 7
// speedup vs baseline: 3.0671x; 1.0685x over previous
#include <cuda_runtime.h>
#include <cuda_bf16.h>
#include <cstdint>

#define TT 2048
#define DD 512
#define MM 8192

// ---------------- scratch (device globals) ----------------------------------
__device__ __nv_bfloat16 g_xh[MM * DD], g_xl[MM * DD];
__device__ __nv_bfloat16 g_wqh[DD * DD], g_wql[DD * DD];
__device__ __nv_bfloat16 g_wkh[DD * DD], g_wkl[DD * DD];
__device__ __nv_bfloat16 g_wvh[DD * DD], g_wvl[DD * DD];
__device__ __nv_bfloat16 g_woh[DD * DD], g_wol[DD * DD];
__device__ __nv_bfloat16 g_Qh[32 * TT * 64], g_Ql[32 * TT * 64];
__device__ __nv_bfloat16 g_Kh[32 * TT * 64], g_Kl[32 * TT * 64];
__device__ __nv_bfloat16 g_Vth[32 * 64 * TT], g_Vtl[32 * 64 * TT]; // [bh][d][t]
__device__ __nv_bfloat16 g_Ch[MM * DD], g_Cl[MM * DD];

// ---------------- helpers ----------------------------------------------------
__device__ __forceinline__ uint32_t smem_u32(const void* p) {
    uint32_t a;
    asm("{ .reg .u64 t; cvta.to.shared.u64 t, %1; cvt.u32.u64 %0, t; }"
        : "=r"(a) : "l"(p));
    return a;
}

#define SWZ(b) ((b) ^ (((b) >> 3) & 0x70))

#define CP16(d, s) asm volatile("cp.async.cg.shared.global [%0], [%1], 16;" :: "r"(d), "l"(s))
#define CPC()      asm volatile("cp.async.commit_group;" ::: "memory")
#define CPW(n)     asm volatile("cp.async.wait_group %0;" :: "n"(n) : "memory")

#define LDSM4(R, addr)                                                         \
    asm volatile("ldmatrix.sync.aligned.m8n8.x4.shared.b16 {%0,%1,%2,%3}, [%4];" \
        : "=r"((R)[0]), "=r"((R)[1]), "=r"((R)[2]), "=r"((R)[3]) : "r"(addr))

#define MMA(C, A, b0, b1)                                                      \
    asm volatile("mma.sync.aligned.m16n8k16.row.col.f32.bf16.bf16.f32 "        \
        "{%0,%1,%2,%3}, {%4,%5,%6,%7}, {%8,%9}, {%0,%1,%2,%3};"                \
        : "+f"((C)[0]), "+f"((C)[1]), "+f"((C)[2]), "+f"((C)[3])               \
        : "r"((A)[0]), "r"((A)[1]), "r"((A)[2]), "r"((A)[3]), "r"(b0), "r"(b1))

__device__ __forceinline__ uint32_t pack2(float lo_e, float hi_e) {
    uint32_t r;
    asm("cvt.rn.bf16x2.f32 %0, %1, %2;" : "=r"(r) : "f"(hi_e), "f"(lo_e));
    return r;
}

__device__ __forceinline__ uint32_t a_addr(uint32_t base, int m0, int k0, int lane) {
    int lr = (lane & 7) + (((lane >> 3) & 1) << 3);
    int lc = ((lane >> 4) & 1) << 3;
    return base + SWZ((uint32_t)((m0 + lr) * 128 + (k0 + lc) * 2));
}
__device__ __forceinline__ uint32_t b_addr(uint32_t base, int n0, int k0, int lane) {
    int lr = (lane & 7) + (((lane >> 4) & 1) << 3);
    int lc = ((lane >> 3) & 1) << 3;
    return base + SWZ((uint32_t)((n0 + lr) * 128 + (k0 + lc) * 2));
}

// ---------------- fp32 -> bf16 hi/lo split (vectorized) ----------------------
__device__ __forceinline__ void cvt4_one(const float4* __restrict__ src,
                                         uint2* __restrict__ dh,
                                         uint2* __restrict__ dl, int i) {
    float4 v = src[i];
    uint32_t h01 = pack2(v.x, v.y);
    uint32_t h23 = pack2(v.z, v.w);
    float r0 = v.x - __uint_as_float(h01 << 16);
    float r1 = v.y - __uint_as_float(h01 & 0xffff0000u);
    float r2 = v.z - __uint_as_float(h23 << 16);
    float r3 = v.w - __uint_as_float(h23 & 0xffff0000u);
    dh[i] = make_uint2(h01, h23);
    dl[i] = make_uint2(pack2(r0, r1), pack2(r2, r3));
}

__global__ void cvt_x(const float* __restrict__ src,
                      __nv_bfloat16* __restrict__ dh,
                      __nv_bfloat16* __restrict__ dl, int n4) {
    for (int i = blockIdx.x * blockDim.x + threadIdx.x; i < n4;
         i += gridDim.x * blockDim.x)
        cvt4_one((const float4*)src, (uint2*)dh, (uint2*)dl, i);
}

__global__ void cvt_w(const float* s0, const float* s1, const float* s2, const float* s3,
                      __nv_bfloat16* h0, __nv_bfloat16* l0,
                      __nv_bfloat16* h1, __nv_bfloat16* l1,
                      __nv_bfloat16* h2, __nv_bfloat16* l2,
                      __nv_bfloat16* h3, __nv_bfloat16* l3) {
    const float* s; __nv_bfloat16 *h, *l;
    switch (blockIdx.y) {
        case 0:  s = s0; h = h0; l = l0; break;
        case 1:  s = s1; h = h1; l = l1; break;
        case 2:  s = s2; h = h2; l = l2; break;
        default: s = s3; h = h3; l = l3; break;
    }
    const int n4 = DD * DD / 4;
    for (int i = blockIdx.x * blockDim.x + threadIdx.x; i < n4;
         i += gridDim.x * blockDim.x)
        cvt4_one((const float4*)s, (uint2*)h, (uint2*)l, i);
}

// ---------------- cp.async tile loader: nrows x 64 bf16 (128B rows), SW128 ---
__device__ __forceinline__ void cp_rows(uint32_t dst, const __nv_bfloat16* src,
                                        int nrows, size_t row_stride,
                                        int tid, int step) {
#pragma unroll 4
    for (int i = tid; i < nrows * 8; i += step) {
        int row = i >> 3, seg = i & 7;
        CP16(dst + SWZ((uint32_t)(row * 128 + seg * 16)),
             src + (size_t)row * row_stride + seg * 8);
    }
}

// ---------------- GEMM: out = A @ W^T + bias (hi/lo 3-split, 2-stage) --------
// mode 0: fp32 [M,512]; mode 1: per-head hi/lo [bh][t][64]; mode 2: V^T [bh][d][t]
#define G_AH 0
#define G_AL 16384
#define G_BH 32768
#define G_BL 49152
#define G_SS 65536
#define G_SMEM 131072

__global__ void __launch_bounds__(256)
gemm_mma(const __nv_bfloat16* __restrict__ Ah, const __nv_bfloat16* __restrict__ Al,
         const __nv_bfloat16* __restrict__ Bh, const __nv_bfloat16* __restrict__ Bl,
         const float* __restrict__ bias, float scale, int mode,
         float* __restrict__ outF,
         __nv_bfloat16* __restrict__ outH, __nv_bfloat16* __restrict__ outL)
{
    extern __shared__ char sm[];
    const uint32_t sb = smem_u32(sm);
    const int tid = threadIdx.x, lane = tid & 31, wid = tid >> 5;
    const int wm = wid >> 1, wn = wid & 1;
    const int m0w = wm * 32, n0w = wn * 64;
    const int m0 = blockIdx.x * 128, n0 = blockIdx.y * 128;

    float c[2][8][4];
#pragma unroll
    for (int a = 0; a < 2; a++)
#pragma unroll
        for (int b = 0; b < 8; b++)
#pragma unroll
            for (int d = 0; d < 4; d++) c[a][b][d] = 0.f;

    // prologue: stage 0
    {
        uint32_t s0 = sb;
        cp_rows(s0 + G_AH, Ah + (size_t)m0 * DD, 128, DD, tid, 256);
        cp_rows(s0 + G_AL, Al + (size_t)m0 * DD, 128, DD, tid, 256);
        cp_rows(s0 + G_BH, Bh + (size_t)n0 * DD, 128, DD, tid, 256);
        cp_rows(s0 + G_BL, Bl + (size_t)n0 * DD, 128, DD, tid, 256);
        CPC();
    }

    for (int ch = 0; ch < 8; ch++) {
        if (ch < 7) {
            uint32_t sn = sb + ((ch + 1) & 1) * G_SS;
            cp_rows(sn + G_AH, Ah + (size_t)m0 * DD + (ch + 1) * 64, 128, DD, tid, 256);
            cp_rows(sn + G_AL, Al + (size_t)m0 * DD + (ch + 1) * 64, 128, DD, tid, 256);
            cp_rows(sn + G_BH, Bh + (size_t)n0 * DD + (ch + 1) * 64, 128, DD, tid, 256);
            cp_rows(sn + G_BL, Bl + (size_t)n0 * DD + (ch + 1) * 64, 128, DD, tid, 256);
            CPC();
            CPW(1);
        } else {
            CPW(0);
        }
        __syncthreads();
        const uint32_t sc = sb + (ch & 1) * G_SS;
#pragma unroll
        for (int kf = 0; kf < 4; kf++) {
            uint32_t ah[2][4], al[2][4];
#pragma unroll
            for (int mi = 0; mi < 2; mi++) {
                LDSM4(ah[mi], a_addr(sc + G_AH, m0w + mi * 16, kf * 16, lane));
                LDSM4(al[mi], a_addr(sc + G_AL, m0w + mi * 16, kf * 16, lane));
            }
#pragma unroll
            for (int np = 0; np < 4; np++) {
                uint32_t bh4[4], bl4[4];
                LDSM4(bh4, b_addr(sc + G_BH, n0w + np * 16, kf * 16, lane));
                LDSM4(bl4, b_addr(sc + G_BL, n0w + np * 16, kf * 16, lane));
#pragma unroll
                for (int mi = 0; mi < 2; mi++) {
                    MMA(c[mi][2 * np],     ah[mi], bh4[0], bh4[1]);
                    MMA(c[mi][2 * np + 1], ah[mi], bh4[2], bh4[3]);
                    MMA(c[mi][2 * np],     ah[mi], bl4[0], bl4[1]);
                    MMA(c[mi][2 * np + 1], ah[mi], bl4[2], bl4[3]);
                    MMA(c[mi][2 * np],     al[mi], bh4[0], bh4[1]);
                    MMA(c[mi][2 * np + 1], al[mi], bh4[2], bh4[3]);
                }
            }
        }
        __syncthreads();
    }

    const int gid = lane >> 2, tig = lane & 3;
#pragma unroll
    for (int mi = 0; mi < 2; mi++)
#pragma unroll
    for (int rh = 0; rh < 2; rh++) {
        int m = m0 + m0w + mi * 16 + rh * 8 + gid;
        if (mode == 0) {
            float* dst = outF + (size_t)m * DD + n0 + n0w;
#pragma unroll
            for (int j = 0; j < 8; j++) {
                int col = 8 * j + tig * 2;
                float v0 = c[mi][j][rh * 2 + 0] + bias[n0 + n0w + col];
                float v1 = c[mi][j][rh * 2 + 1] + bias[n0 + n0w + col + 1];
                *(float2*)(dst + col) = make_float2(v0, v1);
            }
        } else if (mode == 1) {
            int head = blockIdx.y * 2 + wn;
            int b = m >> 11, t = m & 2047;
            size_t base = ((size_t)(b * 8 + head) * TT + t) * 64;
#pragma unroll
            for (int j = 0; j < 8; j++) {
                int d = 8 * j + tig * 2;
                float v0 = (c[mi][j][rh * 2 + 0] + bias[(head << 6) + d]) * scale;
                float v1 = (c[mi][j][rh * 2 + 1] + bias[(head << 6) + d + 1]) * scale;
                uint32_t h2 = pack2(v0, v1);
                float f0 = __uint_as_float(h2 << 16);
                float f1 = __uint_as_float(h2 & 0xffff0000u);
                uint32_t l2 = pack2(v0 - f0, v1 - f1);
                *(uint32_t*)(outH + base + d) = h2;
                *(uint32_t*)(outL + base + d) = l2;
            }
        } else {
            int head = blockIdx.y * 2 + wn;
            int b = m >> 11, t = m & 2047;
            size_t vb = (size_t)(b * 8 + head) * 64 * TT;
#pragma unroll
            for (int j = 0; j < 8; j++) {
                int d = 8 * j + tig * 2;
#pragma unroll
                for (int e = 0; e < 2; e++) {
                    float v = c[mi][j][rh * 2 + e] + bias[(head << 6) + d + e];
                    __nv_bfloat16 h = __float2bfloat16(v);
                    __nv_bfloat16 l = __float2bfloat16(v - __bfloat162float(h));
                    outH[vb + (size_t)(d + e) * TT + t] = h;
                    outL[vb + (size_t)(d + e) * TT + t] = l;
                }
            }
        }
    }
}

// ---------------- flash attention: 4 warps x 32 q-rows, 64-key tiles ---------
#define AT_QH 0
#define AT_QL 16384
#define AT_ST 32768
#define AT_SS 32768
#define AT_KH 0
#define AT_KL 8192
#define AT_VH 16384
#define AT_VL 24576
#define AT_SMEM 98304

__global__ void __launch_bounds__(128, 2)
attn_mma(const __nv_bfloat16* __restrict__ Qh, const __nv_bfloat16* __restrict__ Ql,
         const __nv_bfloat16* __restrict__ Kh, const __nv_bfloat16* __restrict__ Kl,
         const __nv_bfloat16* __restrict__ Vth, const __nv_bfloat16* __restrict__ Vtl,
         __nv_bfloat16* __restrict__ Ch, __nv_bfloat16* __restrict__ Cl)
{
    extern __shared__ char sm[];
    const uint32_t sb = smem_u32(sm);
    const int tid = threadIdx.x, lane = tid & 31, wid = tid >> 5;  // 4 warps
    const int qt = blockIdx.x, bh = blockIdx.y;
    const size_t hb = (size_t)bh * TT;
    const int gid = lane >> 2, tig = lane & 3;

    // prologue: Q (group 0), kv-stage 0 (group 1)
    cp_rows(sb + AT_QH, Qh + (hb + qt * 128) * 64, 128, 64, tid, 128);
    cp_rows(sb + AT_QL, Ql + (hb + qt * 128) * 64, 128, 64, tid, 128);
    CPC();
    {
        uint32_t s0 = sb + AT_ST;
        cp_rows(s0 + AT_KH, Kh + hb * 64, 64, 64, tid, 128);
        cp_rows(s0 + AT_KL, Kl + hb * 64, 64, 64, tid, 128);
        cp_rows(s0 + AT_VH, Vth + hb * 64, 64, TT, tid, 128);
        cp_rows(s0 + AT_VL, Vtl + hb * 64, 64, TT, tid, 128);
        CPC();
    }
    CPW(1);
    __syncthreads();

    uint32_t qh4[2][4][4], ql4[2][4][4];
#pragma unroll
    for (int mi = 0; mi < 2; mi++)
#pragma unroll
        for (int kf = 0; kf < 4; kf++) {
            LDSM4(qh4[mi][kf], a_addr(sb + AT_QH, wid * 32 + mi * 16, kf * 16, lane));
            LDSM4(ql4[mi][kf], a_addr(sb + AT_QL, wid * 32 + mi * 16, kf * 16, lane));
        }

    float o[2][8][4];
#pragma unroll
    for (int mi = 0; mi < 2; mi++)
#pragma unroll
        for (int j = 0; j < 8; j++)
#pragma unroll
            for (int d = 0; d < 4; d++) o[mi][j][d] = 0.f;
    float mrow[2][2] = {{-1e30f, -1e30f}, {-1e30f, -1e30f}};
    float lrow[2][2] = {{0.f, 0.f}, {0.f, 0.f}};

    for (int kt = 0; kt < 32; kt++) {
        if (kt < 31) {
            uint32_t sn = sb + AT_ST + ((kt + 1) & 1) * AT_SS;
            cp_rows(sn + AT_KH, Kh + (hb + (kt + 1) * 64) * 64, 64, 64, tid, 128);
            cp_rows(sn + AT_KL, Kl + (hb + (kt + 1) * 64) * 64, 64, 64, tid, 128);
            cp_rows(sn + AT_VH, Vth + hb * 64 + (kt + 1) * 64, 64, TT, tid, 128);
            cp_rows(sn + AT_VL, Vtl + hb * 64 + (kt + 1) * 64, 64, TT, tid, 128);
            CPC();
            CPW(1);
        } else {
            CPW(0);
        }
        __syncthreads();
        const uint32_t sc = sb + AT_ST + (kt & 1) * AT_SS;

        // S = Q K^T  (3-split)
        float sa[2][8][4];
#pragma unroll
        for (int mi = 0; mi < 2; mi++)
#pragma unroll
            for (int j = 0; j < 8; j++)
#pragma unroll
                for (int d = 0; d < 4; d++) sa[mi][j][d] = 0.f;
#pragma unroll
        for (int kf = 0; kf < 4; kf++) {
#pragma unroll
            for (int np = 0; np < 4; np++) {
                uint32_t b4[4], bl4[4];
                LDSM4(b4,  b_addr(sc + AT_KH, np * 16, kf * 16, lane));
                LDSM4(bl4, b_addr(sc + AT_KL, np * 16, kf * 16, lane));
#pragma unroll
                for (int mi = 0; mi < 2; mi++) {
                    MMA(sa[mi][2 * np],     qh4[mi][kf], b4[0], b4[1]);
                    MMA(sa[mi][2 * np + 1], qh4[mi][kf], b4[2], b4[3]);
                    MMA(sa[mi][2 * np],     qh4[mi][kf], bl4[0], bl4[1]);
                    MMA(sa[mi][2 * np + 1], qh4[mi][kf], bl4[2], bl4[3]);
                    MMA(sa[mi][2 * np],     ql4[mi][kf], b4[0], b4[1]);
                    MMA(sa[mi][2 * np + 1], ql4[mi][kf], b4[2], b4[3]);
                }
            }
        }

        // online softmax (rows: mi*16 + rh*8 + gid)
#pragma unroll
        for (int mi = 0; mi < 2; mi++)
#pragma unroll
        for (int rh = 0; rh < 2; rh++) {
            float mx = -1e30f;
#pragma unroll
            for (int j = 0; j < 8; j++)
                mx = fmaxf(mx, fmaxf(sa[mi][j][rh * 2], sa[mi][j][rh * 2 + 1]));
            mx = fmaxf(mx, __shfl_xor_sync(0xffffffffu, mx, 1));
            mx = fmaxf(mx, __shfl_xor_sync(0xffffffffu, mx, 2));
            float mnew = fmaxf(mrow[mi][rh], mx);
            float corr = __expf(mrow[mi][rh] - mnew);
            float ps = 0.f;
#pragma unroll
            for (int j = 0; j < 8; j++) {
                float e0 = __expf(sa[mi][j][rh * 2] - mnew);
                float e1 = __expf(sa[mi][j][rh * 2 + 1] - mnew);
                sa[mi][j][rh * 2] = e0;
                sa[mi][j][rh * 2 + 1] = e1;
                ps += e0 + e1;
            }
            ps += __shfl_xor_sync(0xffffffffu, ps, 1);
            ps += __shfl_xor_sync(0xffffffffu, ps, 2);
            lrow[mi][rh] = lrow[mi][rh] * corr + ps;
            mrow[mi][rh] = mnew;
#pragma unroll
            for (int j = 0; j < 8; j++) {
                o[mi][j][rh * 2] *= corr;
                o[mi][j][rh * 2 + 1] *= corr;
            }
        }

        // O += P V  (3-split, P from registers)
#pragma unroll
        for (int kf = 0; kf < 4; kf++) {
            uint32_t pah[2][4], pal[2][4];
#pragma unroll
            for (int mi = 0; mi < 2; mi++)
#pragma unroll
                for (int q = 0; q < 4; q++) {
                    const float* src = (q < 2) ? sa[mi][2 * kf] : sa[mi][2 * kf + 1];
                    float p0 = src[(q & 1) * 2], p1 = src[(q & 1) * 2 + 1];
                    uint32_t h2 = pack2(p0, p1);
                    float f0 = __uint_as_float(h2 << 16);
                    float f1 = __uint_as_float(h2 & 0xffff0000u);
                    pah[mi][q] = h2;
                    pal[mi][q] = pack2(p0 - f0, p1 - f1);
                }
#pragma unroll
            for (int np = 0; np < 4; np++) {
                uint32_t vh4[4], vl4[4];
                LDSM4(vh4, b_addr(sc + AT_VH, np * 16, kf * 16, lane));
                LDSM4(vl4, b_addr(sc + AT_VL, np * 16, kf * 16, lane));
#pragma unroll
                for (int mi = 0; mi < 2; mi++) {
                    MMA(o[mi][2 * np],     pah[mi], vh4[0], vh4[1]);
                    MMA(o[mi][2 * np + 1], pah[mi], vh4[2], vh4[3]);
                    MMA(o[mi][2 * np],     pah[mi], vl4[0], vl4[1]);
                    MMA(o[mi][2 * np + 1], pah[mi], vl4[2], vl4[3]);
                    MMA(o[mi][2 * np],     pal[mi], vh4[0], vh4[1]);
                    MMA(o[mi][2 * np + 1], pal[mi], vh4[2], vh4[3]);
                }
            }
        }
        __syncthreads();
    }

    const int b = bh >> 3, h = bh & 7;
#pragma unroll
    for (int mi = 0; mi < 2; mi++)
#pragma unroll
    for (int rh = 0; rh < 2; rh++) {
        float inv = 1.f / lrow[mi][rh];
        int t = qt * 128 + wid * 32 + mi * 16 + rh * 8 + gid;
        size_t base = ((size_t)(b * TT + t)) * DD + h * 64;
#pragma unroll
        for (int j = 0; j < 8; j++) {
            int d = 8 * j + tig * 2;
            float v0 = o[mi][j][rh * 2] * inv;
            float v1 = o[mi][j][rh * 2 + 1] * inv;
            uint32_t h2 = pack2(v0, v1);
            float f0 = __uint_as_float(h2 << 16);
            float f1 = __uint_as_float(h2 & 0xffff0000u);
            uint32_t l2 = pack2(v0 - f0, v1 - f1);
            *(uint32_t*)(Ch + base + d) = h2;
            *(uint32_t*)(Cl + base + d) = l2;
        }
    }
}

// ---------------------------------------------------------------------------
extern "C" void kernel_launch(void* const* d_in, const int* in_sizes, int n_in,
                              void* d_out, int out_size)
{
    const float* x  = (const float*)d_in[0];
    const float* wq = (const float*)d_in[1];
    const float* bq = (const float*)d_in[2];
    const float* wk = (const float*)d_in[3];
    const float* bk = (const float*)d_in[4];
    const float* wv = (const float*)d_in[5];
    const float* bv = (const float*)d_in[6];
    const float* wo = (const float*)d_in[7];
    const float* bo = (const float*)d_in[8];
    float* out = (float*)d_out;

    __nv_bfloat16 *xh, *xl, *wqh, *wql, *wkh, *wkl, *wvh, *wvl, *woh, *wol;
    __nv_bfloat16 *qh, *ql, *kh, *kl, *vth, *vtl, *ch, *cl;
    cudaGetSymbolAddress((void**)&xh, g_xh);   cudaGetSymbolAddress((void**)&xl, g_xl);
    cudaGetSymbolAddress((void**)&wqh, g_wqh); cudaGetSymbolAddress((void**)&wql, g_wql);
    cudaGetSymbolAddress((void**)&wkh, g_wkh); cudaGetSymbolAddress((void**)&wkl, g_wkl);
    cudaGetSymbolAddress((void**)&wvh, g_wvh); cudaGetSymbolAddress((void**)&wvl, g_wvl);
    cudaGetSymbolAddress((void**)&woh, g_woh); cudaGetSymbolAddress((void**)&wol, g_wol);
    cudaGetSymbolAddress((void**)&qh, g_Qh);   cudaGetSymbolAddress((void**)&ql, g_Ql);
    cudaGetSymbolAddress((void**)&kh, g_Kh);   cudaGetSymbolAddress((void**)&kl, g_Kl);
    cudaGetSymbolAddress((void**)&vth, g_Vth); cudaGetSymbolAddress((void**)&vtl, g_Vtl);
    cudaGetSymbolAddress((void**)&ch, g_Ch);   cudaGetSymbolAddress((void**)&cl, g_Cl);

    cvt_x<<<512, 256>>>(x, xh, xl, MM * DD / 4);
    cvt_w<<<dim3(64, 4), 256>>>(wq, wk, wv, wo, wqh, wql, wkh, wkl,
                                wvh, wvl, woh, wol);

    cudaFuncSetAttribute(gemm_mma, cudaFuncAttributeMaxDynamicSharedMemorySize, G_SMEM);
    cudaFuncSetAttribute(attn_mma, cudaFuncAttributeMaxDynamicSharedMemorySize, AT_SMEM);

    dim3 gg(MM / 128, DD / 128);
    gemm_mma<<<gg, 256, G_SMEM>>>(xh, xl, wqh, wql, bq, 0.125f, 1, nullptr, qh, ql);
    gemm_mma<<<gg, 256, G_SMEM>>>(xh, xl, wkh, wkl, bk, 1.0f,   1, nullptr, kh, kl);
    gemm_mma<<<gg, 256, G_SMEM>>>(xh, xl, wvh, wvl, bv, 1.0f,   2, nullptr, vth, vtl);

    attn_mma<<<dim3(TT / 128, 32), 128, AT_SMEM>>>(qh, ql, kh, kl, vth, vtl, ch, cl);

    gemm_mma<<<gg, 256, G_SMEM>>>(ch, cl, woh, wol, bo, 1.0f, 0, out, nullptr, nullptr);
}

// round 8
// speedup vs baseline: 3.4696x; 1.1312x over previous
#include <cuda_runtime.h>
#include <cuda_bf16.h>
#include <cstdint>

#define TT 2048
#define DD 512
#define MM 8192

// ---------------- scratch (device globals) ----------------------------------
__device__ __nv_bfloat16 g_xh[MM * DD], g_xl[MM * DD];
__device__ __nv_bfloat16 g_wqh[DD * DD], g_wql[DD * DD];
__device__ __nv_bfloat16 g_wkh[DD * DD], g_wkl[DD * DD];
__device__ __nv_bfloat16 g_wvh[DD * DD], g_wvl[DD * DD];
__device__ __nv_bfloat16 g_woh[DD * DD], g_wol[DD * DD];
__device__ __nv_bfloat16 g_Qh[32 * TT * 64], g_Ql[32 * TT * 64];
__device__ __nv_bfloat16 g_Kh[32 * TT * 64], g_Kl[32 * TT * 64];
__device__ __nv_bfloat16 g_Vth[32 * 64 * TT], g_Vtl[32 * 64 * TT]; // [bh][d][t]
__device__ __nv_bfloat16 g_Ch[MM * DD], g_Cl[MM * DD];

// ---------------- helpers ----------------------------------------------------
__device__ __forceinline__ uint32_t smem_u32(const void* p) {
    uint32_t a;
    asm("{ .reg .u64 t; cvta.to.shared.u64 t, %1; cvt.u32.u64 %0, t; }"
        : "=r"(a) : "l"(p));
    return a;
}

#define SWZ(b) ((b) ^ (((b) >> 3) & 0x70))

#define CP16(d, s) asm volatile("cp.async.cg.shared.global [%0], [%1], 16;" :: "r"(d), "l"(s))
#define CPC()      asm volatile("cp.async.commit_group;" ::: "memory")
#define CPW(n)     asm volatile("cp.async.wait_group %0;" :: "n"(n) : "memory")

#define LDSM4(R, addr)                                                         \
    asm volatile("ldmatrix.sync.aligned.m8n8.x4.shared.b16 {%0,%1,%2,%3}, [%4];" \
        : "=r"((R)[0]), "=r"((R)[1]), "=r"((R)[2]), "=r"((R)[3]) : "r"(addr))

#define MMA(C, A, b0, b1)                                                      \
    asm volatile("mma.sync.aligned.m16n8k16.row.col.f32.bf16.bf16.f32 "        \
        "{%0,%1,%2,%3}, {%4,%5,%6,%7}, {%8,%9}, {%0,%1,%2,%3};"                \
        : "+f"((C)[0]), "+f"((C)[1]), "+f"((C)[2]), "+f"((C)[3])               \
        : "r"((A)[0]), "r"((A)[1]), "r"((A)[2]), "r"((A)[3]), "r"(b0), "r"(b1))

__device__ __forceinline__ uint32_t pack2(float lo_e, float hi_e) {
    uint32_t r;
    asm("cvt.rn.bf16x2.f32 %0, %1, %2;" : "=r"(r) : "f"(hi_e), "f"(lo_e));
    return r;
}
__device__ __forceinline__ float ex2(float x) {
    float y;
    asm("ex2.approx.f32 %0, %1;" : "=f"(y) : "f"(x));
    return y;
}

__device__ __forceinline__ uint32_t a_addr(uint32_t base, int m0, int k0, int lane) {
    int lr = (lane & 7) + (((lane >> 3) & 1) << 3);
    int lc = ((lane >> 4) & 1) << 3;
    return base + SWZ((uint32_t)((m0 + lr) * 128 + (k0 + lc) * 2));
}
__device__ __forceinline__ uint32_t b_addr(uint32_t base, int n0, int k0, int lane) {
    int lr = (lane & 7) + (((lane >> 4) & 1) << 3);
    int lc = ((lane >> 3) & 1) << 3;
    return base + SWZ((uint32_t)((n0 + lr) * 128 + (k0 + lc) * 2));
}

// ---------------- fp32 -> bf16 hi/lo split (vectorized) ----------------------
__device__ __forceinline__ void cvt4_one(const float4* __restrict__ src,
                                         uint2* __restrict__ dh,
                                         uint2* __restrict__ dl, int i) {
    float4 v = src[i];
    uint32_t h01 = pack2(v.x, v.y);
    uint32_t h23 = pack2(v.z, v.w);
    float r0 = v.x - __uint_as_float(h01 << 16);
    float r1 = v.y - __uint_as_float(h01 & 0xffff0000u);
    float r2 = v.z - __uint_as_float(h23 << 16);
    float r3 = v.w - __uint_as_float(h23 & 0xffff0000u);
    dh[i] = make_uint2(h01, h23);
    dl[i] = make_uint2(pack2(r0, r1), pack2(r2, r3));
}

__global__ void cvt_x(const float* __restrict__ src,
                      __nv_bfloat16* __restrict__ dh,
                      __nv_bfloat16* __restrict__ dl, int n4) {
    for (int i = blockIdx.x * blockDim.x + threadIdx.x; i < n4;
         i += gridDim.x * blockDim.x)
        cvt4_one((const float4*)src, (uint2*)dh, (uint2*)dl, i);
}

__global__ void cvt_w(const float* s0, const float* s1, const float* s2, const float* s3,
                      __nv_bfloat16* h0, __nv_bfloat16* l0,
                      __nv_bfloat16* h1, __nv_bfloat16* l1,
                      __nv_bfloat16* h2, __nv_bfloat16* l2,
                      __nv_bfloat16* h3, __nv_bfloat16* l3) {
    const float* s; __nv_bfloat16 *h, *l;
    switch (blockIdx.y) {
        case 0:  s = s0; h = h0; l = l0; break;
        case 1:  s = s1; h = h1; l = l1; break;
        case 2:  s = s2; h = h2; l = l2; break;
        default: s = s3; h = h3; l = l3; break;
    }
    const int n4 = DD * DD / 4;
    for (int i = blockIdx.x * blockDim.x + threadIdx.x; i < n4;
         i += gridDim.x * blockDim.x)
        cvt4_one((const float4*)s, (uint2*)h, (uint2*)l, i);
}

// ---------------- cp.async tile loader: nrows x 64 bf16 (128B rows), SW128 ---
__device__ __forceinline__ void cp_rows(uint32_t dst, const __nv_bfloat16* src,
                                        int nrows, size_t row_stride,
                                        int tid, int step) {
#pragma unroll 4
    for (int i = tid; i < nrows * 8; i += step) {
        int row = i >> 3, seg = i & 7;
        CP16(dst + SWZ((uint32_t)(row * 128 + seg * 16)),
             src + (size_t)row * row_stride + seg * 8);
    }
}

// ---------------- GEMM: m64 x n128 tile, k64 chunks, 2-stage, 2 CTA/SM -------
// mode 0: fp32 [M,512]; mode 1: per-head hi/lo [bh][t][64]; mode 2: V^T [bh][d][t]
#define G_AH 0
#define G_AL 8192
#define G_BH 16384
#define G_BL 32768
#define G_SS 49152
#define G_SMEM 98304

__global__ void __launch_bounds__(256, 2)
gemm_mma(const __nv_bfloat16* __restrict__ Ah, const __nv_bfloat16* __restrict__ Al,
         const __nv_bfloat16* __restrict__ Bh, const __nv_bfloat16* __restrict__ Bl,
         const float* __restrict__ bias, float scale, int mode,
         float* __restrict__ outF,
         __nv_bfloat16* __restrict__ outH, __nv_bfloat16* __restrict__ outL)
{
    extern __shared__ char sm[];
    const uint32_t sb = smem_u32(sm);
    const int tid = threadIdx.x, lane = tid & 31, wid = tid >> 5;
    const int wm = wid >> 2, wn = wid & 3;      // 2 x 4 warp grid
    const int m0w = wm * 32, n0w = wn * 32;
    const int m0 = blockIdx.x * 64, n0 = blockIdx.y * 128;

    float c[2][4][4];
#pragma unroll
    for (int a = 0; a < 2; a++)
#pragma unroll
        for (int b = 0; b < 4; b++)
#pragma unroll
            for (int d = 0; d < 4; d++) c[a][b][d] = 0.f;

    // prologue: stage 0
    cp_rows(sb + G_AH, Ah + (size_t)m0 * DD, 64, DD, tid, 256);
    cp_rows(sb + G_AL, Al + (size_t)m0 * DD, 64, DD, tid, 256);
    cp_rows(sb + G_BH, Bh + (size_t)n0 * DD, 128, DD, tid, 256);
    cp_rows(sb + G_BL, Bl + (size_t)n0 * DD, 128, DD, tid, 256);
    CPC();

    for (int ch = 0; ch < 8; ch++) {
        if (ch < 7) {
            uint32_t sn = sb + ((ch + 1) & 1) * G_SS;
            cp_rows(sn + G_AH, Ah + (size_t)m0 * DD + (ch + 1) * 64, 64, DD, tid, 256);
            cp_rows(sn + G_AL, Al + (size_t)m0 * DD + (ch + 1) * 64, 64, DD, tid, 256);
            cp_rows(sn + G_BH, Bh + (size_t)n0 * DD + (ch + 1) * 64, 128, DD, tid, 256);
            cp_rows(sn + G_BL, Bl + (size_t)n0 * DD + (ch + 1) * 64, 128, DD, tid, 256);
            CPC();
            CPW(1);
        } else {
            CPW(0);
        }
        __syncthreads();
        const uint32_t sc = sb + (ch & 1) * G_SS;
#pragma unroll
        for (int kf = 0; kf < 4; kf++) {
            uint32_t ah[2][4], al[2][4];
#pragma unroll
            for (int mi = 0; mi < 2; mi++) {
                LDSM4(ah[mi], a_addr(sc + G_AH, m0w + mi * 16, kf * 16, lane));
                LDSM4(al[mi], a_addr(sc + G_AL, m0w + mi * 16, kf * 16, lane));
            }
#pragma unroll
            for (int np = 0; np < 2; np++) {
                uint32_t bh4[4], bl4[4];
                LDSM4(bh4, b_addr(sc + G_BH, n0w + np * 16, kf * 16, lane));
                LDSM4(bl4, b_addr(sc + G_BL, n0w + np * 16, kf * 16, lane));
#pragma unroll
                for (int mi = 0; mi < 2; mi++) {
                    MMA(c[mi][2 * np],     ah[mi], bh4[0], bh4[1]);
                    MMA(c[mi][2 * np + 1], ah[mi], bh4[2], bh4[3]);
                    MMA(c[mi][2 * np],     ah[mi], bl4[0], bl4[1]);
                    MMA(c[mi][2 * np + 1], ah[mi], bl4[2], bl4[3]);
                    MMA(c[mi][2 * np],     al[mi], bh4[0], bh4[1]);
                    MMA(c[mi][2 * np + 1], al[mi], bh4[2], bh4[3]);
                }
            }
        }
        __syncthreads();
    }

    const int gid = lane >> 2, tig = lane & 3;
#pragma unroll
    for (int mi = 0; mi < 2; mi++)
#pragma unroll
    for (int rh = 0; rh < 2; rh++) {
        int m = m0 + m0w + mi * 16 + rh * 8 + gid;
        if (mode == 0) {
            float* dst = outF + (size_t)m * DD + n0 + n0w;
#pragma unroll
            for (int j = 0; j < 4; j++) {
                int col = 8 * j + tig * 2;
                float v0 = c[mi][j][rh * 2 + 0] + bias[n0 + n0w + col];
                float v1 = c[mi][j][rh * 2 + 1] + bias[n0 + n0w + col + 1];
                *(float2*)(dst + col) = make_float2(v0, v1);
            }
        } else if (mode == 1) {
            int b = m >> 11, t = m & 2047;
#pragma unroll
            for (int j = 0; j < 4; j++) {
                int gn = n0 + n0w + 8 * j + tig * 2;
                int head = gn >> 6, d = gn & 63;
                size_t base = ((size_t)(b * 8 + head) * TT + t) * 64;
                float v0 = (c[mi][j][rh * 2 + 0] + bias[gn]) * scale;
                float v1 = (c[mi][j][rh * 2 + 1] + bias[gn + 1]) * scale;
                uint32_t h2 = pack2(v0, v1);
                float f0 = __uint_as_float(h2 << 16);
                float f1 = __uint_as_float(h2 & 0xffff0000u);
                uint32_t l2 = pack2(v0 - f0, v1 - f1);
                *(uint32_t*)(outH + base + d) = h2;
                *(uint32_t*)(outL + base + d) = l2;
            }
        } else {
            int b = m >> 11, t = m & 2047;
#pragma unroll
            for (int j = 0; j < 4; j++) {
                int gn = n0 + n0w + 8 * j + tig * 2;
                int head = gn >> 6, d = gn & 63;
                size_t vb = (size_t)(b * 8 + head) * 64 * TT;
#pragma unroll
                for (int e = 0; e < 2; e++) {
                    float v = c[mi][j][rh * 2 + e] + bias[gn + e];
                    __nv_bfloat16 h = __float2bfloat16(v);
                    __nv_bfloat16 l = __float2bfloat16(v - __bfloat162float(h));
                    outH[vb + (size_t)(d + e) * TT + t] = h;
                    outL[vb + (size_t)(d + e) * TT + t] = l;
                }
            }
        }
    }
}

// ---------------- flash attention: 4 warps x 16 q-rows, 64-key tiles, --------
// K and V double-buffered; Q smem region reused as V0 buffer. 3 CTAs/SM.
// smem map: [0,16K) Q (later V even stages), [16K,32K) K even, [32K,48K) K odd,
//           [48K,64K) V odd.  Each 16K region = {hi 8K, lo 8K}.
#define AT_SMEM 65536

__global__ void __launch_bounds__(128, 3)
attn_mma(const __nv_bfloat16* __restrict__ Qh, const __nv_bfloat16* __restrict__ Ql,
         const __nv_bfloat16* __restrict__ Kh, const __nv_bfloat16* __restrict__ Kl,
         const __nv_bfloat16* __restrict__ Vth, const __nv_bfloat16* __restrict__ Vtl,
         __nv_bfloat16* __restrict__ Ch, __nv_bfloat16* __restrict__ Cl)
{
    extern __shared__ char sm[];
    const uint32_t sb = smem_u32(sm);
    const int tid = threadIdx.x, lane = tid & 31, wid = tid >> 5;  // 4 warps
    const int qt = blockIdx.x, bh = blockIdx.y;
    const size_t hb = (size_t)bh * TT;
    const size_t vB = (size_t)bh * 64 * TT;
    const int gid = lane >> 2, tig = lane & 3;

    // prologue: Q, then K0
    cp_rows(sb + 0,    Qh + (hb + qt * 64) * 64, 64, 64, tid, 128);
    cp_rows(sb + 8192, Ql + (hb + qt * 64) * 64, 64, 64, tid, 128);
    CPC();
    cp_rows(sb + 16384, Kh + hb * 64, 64, 64, tid, 128);
    cp_rows(sb + 24576, Kl + hb * 64, 64, 64, tid, 128);
    CPC();
    CPW(1);                  // Q ready
    __syncthreads();

    uint32_t qh4[4][4], ql4[4][4];
#pragma unroll
    for (int kf = 0; kf < 4; kf++) {
        LDSM4(qh4[kf], a_addr(sb + 0,    wid * 16, kf * 16, lane));
        LDSM4(ql4[kf], a_addr(sb + 8192, wid * 16, kf * 16, lane));
    }
    __syncthreads();         // Q region free -> becomes V even buffer

    cp_rows(sb + 0,    Vth + vB, 64, TT, tid, 128);
    cp_rows(sb + 8192, Vtl + vB, 64, TT, tid, 128);
    CPC();

    float o[8][4];
#pragma unroll
    for (int j = 0; j < 8; j++)
#pragma unroll
        for (int d = 0; d < 4; d++) o[j][d] = 0.f;
    float mrow[2] = {-1e30f, -1e30f}, lrow[2] = {0.f, 0.f};

    for (int kt = 0; kt < 32; kt++) {
        CPW(0);              // K_kt and V_kt resident
        __syncthreads();
        const uint32_t kc = sb + 16384 + (kt & 1) * 16384;
        const uint32_t vc = (kt & 1) ? sb + 49152 : sb + 0;

        // S = Q K^T  (3-split)
        float sa[8][4];
#pragma unroll
        for (int j = 0; j < 8; j++)
#pragma unroll
            for (int d = 0; d < 4; d++) sa[j][d] = 0.f;
#pragma unroll
        for (int kf = 0; kf < 4; kf++) {
#pragma unroll
            for (int np = 0; np < 4; np++) {
                uint32_t b4[4], bl4[4];
                LDSM4(b4,  b_addr(kc,        np * 16, kf * 16, lane));
                LDSM4(bl4, b_addr(kc + 8192, np * 16, kf * 16, lane));
                MMA(sa[2 * np],     qh4[kf], b4[0], b4[1]);
                MMA(sa[2 * np + 1], qh4[kf], b4[2], b4[3]);
                MMA(sa[2 * np],     qh4[kf], bl4[0], bl4[1]);
                MMA(sa[2 * np + 1], qh4[kf], bl4[2], bl4[3]);
                MMA(sa[2 * np],     ql4[kf], b4[0], b4[1]);
                MMA(sa[2 * np + 1], ql4[kf], b4[2], b4[3]);
            }
        }

        // prefetch next K/V (other buffers; safe after top-of-iter barrier)
        if (kt < 31) {
            uint32_t kn = sb + 16384 + ((kt + 1) & 1) * 16384;
            uint32_t vn = ((kt + 1) & 1) ? sb + 49152 : sb + 0;
            cp_rows(kn,        Kh + (hb + (kt + 1) * 64) * 64, 64, 64, tid, 128);
            cp_rows(kn + 8192, Kl + (hb + (kt + 1) * 64) * 64, 64, 64, tid, 128);
            cp_rows(vn,        Vth + vB + (kt + 1) * 64, 64, TT, tid, 128);
            cp_rows(vn + 8192, Vtl + vB + (kt + 1) * 64, 64, TT, tid, 128);
            CPC();
        }

        // online softmax (base-2 logits; rows rh*8 + gid within warp q-rows)
#pragma unroll
        for (int rh = 0; rh < 2; rh++) {
            float mx = -1e30f;
#pragma unroll
            for (int j = 0; j < 8; j++)
                mx = fmaxf(mx, fmaxf(sa[j][rh * 2], sa[j][rh * 2 + 1]));
            mx = fmaxf(mx, __shfl_xor_sync(0xffffffffu, mx, 1));
            mx = fmaxf(mx, __shfl_xor_sync(0xffffffffu, mx, 2));
            float mnew = fmaxf(mrow[rh], mx);
            float corr = ex2(mrow[rh] - mnew);
            float ps = 0.f;
#pragma unroll
            for (int j = 0; j < 8; j++) {
                float e0 = ex2(sa[j][rh * 2] - mnew);
                float e1 = ex2(sa[j][rh * 2 + 1] - mnew);
                sa[j][rh * 2] = e0;
                sa[j][rh * 2 + 1] = e1;
                ps += e0 + e1;
            }
            ps += __shfl_xor_sync(0xffffffffu, ps, 1);
            ps += __shfl_xor_sync(0xffffffffu, ps, 2);
            lrow[rh] = lrow[rh] * corr + ps;
            mrow[rh] = mnew;
#pragma unroll
            for (int j = 0; j < 8; j++) {
                o[j][rh * 2] *= corr;
                o[j][rh * 2 + 1] *= corr;
            }
        }

        // O += P V  (3-split, P from registers)
#pragma unroll
        for (int kf = 0; kf < 4; kf++) {
            uint32_t pah[4], pal[4];
#pragma unroll
            for (int q = 0; q < 4; q++) {
                const float* src = (q < 2) ? sa[2 * kf] : sa[2 * kf + 1];
                float p0 = src[(q & 1) * 2], p1 = src[(q & 1) * 2 + 1];
                uint32_t h2 = pack2(p0, p1);
                float f0 = __uint_as_float(h2 << 16);
                float f1 = __uint_as_float(h2 & 0xffff0000u);
                pah[q] = h2;
                pal[q] = pack2(p0 - f0, p1 - f1);
            }
#pragma unroll
            for (int np = 0; np < 4; np++) {
                uint32_t vh4[4], vl4[4];
                LDSM4(vh4, b_addr(vc,        np * 16, kf * 16, lane));
                LDSM4(vl4, b_addr(vc + 8192, np * 16, kf * 16, lane));
                MMA(o[2 * np],     pah, vh4[0], vh4[1]);
                MMA(o[2 * np + 1], pah, vh4[2], vh4[3]);
                MMA(o[2 * np],     pah, vl4[0], vl4[1]);
                MMA(o[2 * np + 1], pah, vl4[2], vl4[3]);
                MMA(o[2 * np],     pal, vh4[0], vh4[1]);
                MMA(o[2 * np + 1], pal, vh4[2], vh4[3]);
            }
        }
    }

    const int b = bh >> 3, h = bh & 7;
#pragma unroll
    for (int rh = 0; rh < 2; rh++) {
        float inv = 1.f / lrow[rh];
        int t = qt * 64 + wid * 16 + rh * 8 + gid;
        size_t base = ((size_t)(b * TT + t)) * DD + h * 64;
#pragma unroll
        for (int j = 0; j < 8; j++) {
            int d = 8 * j + tig * 2;
            float v0 = o[j][rh * 2] * inv;
            float v1 = o[j][rh * 2 + 1] * inv;
            uint32_t h2 = pack2(v0, v1);
            float f0 = __uint_as_float(h2 << 16);
            float f1 = __uint_as_float(h2 & 0xffff0000u);
            uint32_t l2 = pack2(v0 - f0, v1 - f1);
            *(uint32_t*)(Ch + base + d) = h2;
            *(uint32_t*)(Cl + base + d) = l2;
        }
    }
}

// ---------------------------------------------------------------------------
extern "C" void kernel_launch(void* const* d_in, const int* in_sizes, int n_in,
                              void* d_out, int out_size)
{
    const float* x  = (const float*)d_in[0];
    const float* wq = (const float*)d_in[1];
    const float* bq = (const float*)d_in[2];
    const float* wk = (const float*)d_in[3];
    const float* bk = (const float*)d_in[4];
    const float* wv = (const float*)d_in[5];
    const float* bv = (const float*)d_in[6];
    const float* wo = (const float*)d_in[7];
    const float* bo = (const float*)d_in[8];
    float* out = (float*)d_out;

    __nv_bfloat16 *xh, *xl, *wqh, *wql, *wkh, *wkl, *wvh, *wvl, *woh, *wol;
    __nv_bfloat16 *qh, *ql, *kh, *kl, *vth, *vtl, *ch, *cl;
    cudaGetSymbolAddress((void**)&xh, g_xh);   cudaGetSymbolAddress((void**)&xl, g_xl);
    cudaGetSymbolAddress((void**)&wqh, g_wqh); cudaGetSymbolAddress((void**)&wql, g_wql);
    cudaGetSymbolAddress((void**)&wkh, g_wkh); cudaGetSymbolAddress((void**)&wkl, g_wkl);
    cudaGetSymbolAddress((void**)&wvh, g_wvh); cudaGetSymbolAddress((void**)&wvl, g_wvl);
    cudaGetSymbolAddress((void**)&woh, g_woh); cudaGetSymbolAddress((void**)&wol, g_wol);
    cudaGetSymbolAddress((void**)&qh, g_Qh);   cudaGetSymbolAddress((void**)&ql, g_Ql);
    cudaGetSymbolAddress((void**)&kh, g_Kh);   cudaGetSymbolAddress((void**)&kl, g_Kl);
    cudaGetSymbolAddress((void**)&vth, g_Vth); cudaGetSymbolAddress((void**)&vtl, g_Vtl);
    cudaGetSymbolAddress((void**)&ch, g_Ch);   cudaGetSymbolAddress((void**)&cl, g_Cl);

    cvt_x<<<512, 256>>>(x, xh, xl, MM * DD / 4);
    cvt_w<<<dim3(64, 4), 256>>>(wq, wk, wv, wo, wqh, wql, wkh, wkl,
                                wvh, wvl, woh, wol);

    cudaFuncSetAttribute(gemm_mma, cudaFuncAttributeMaxDynamicSharedMemorySize, G_SMEM);
    cudaFuncSetAttribute(attn_mma, cudaFuncAttributeMaxDynamicSharedMemorySize, AT_SMEM);

    dim3 gg(MM / 64, DD / 128);                 // 128 x 4
    const float qs = 0.125f * 1.44269504f;      // 1/sqrt(64) * log2(e)

    gemm_mma<<<gg, 256, G_SMEM>>>(xh, xl, wqh, wql, bq, qs,   1, nullptr, qh, ql);
    gemm_mma<<<gg, 256, G_SMEM>>>(xh, xl, wkh, wkl, bk, 1.0f, 1, nullptr, kh, kl);
    gemm_mma<<<gg, 256, G_SMEM>>>(xh, xl, wvh, wvl, bv, 1.0f, 2, nullptr, vth, vtl);

    attn_mma<<<dim3(TT / 64, 32), 128, AT_SMEM>>>(qh, ql, kh, kl, vth, vtl, ch, cl);

    gemm_mma<<<gg, 256, G_SMEM>>>(ch, cl, woh, wol, bo, 1.0f, 0, out, nullptr, nullptr);
}